// round 3
// baseline (speedup 1.0000x reference)
#include <cuda_runtime.h>
#include <math.h>

#define S    2048
#define HID  2048
#define NH   16
#define HD   128
#define DC   256      // concatenated per-head dim (mu 128 + sigma 128)

#define BM 128
#define BN 128
#define BK 8

// ---------------- scratch (static device globals; no allocation) ----------------
__device__ float g_qcat[NH * S * DC];        // [H][S][256]  (q_mu roped | sig_q)
__device__ float g_kcat[NH * S * DC];        // [H][S][256]  (k_mu roped | sig_k)
__device__ float g_vcat[NH * S * DC];        // [H][S][256]  (v_mu | v_ls)
__device__ float g_P[NH * S * S];            // [H][S][S] logits -> probs (256MB)
__device__ float g_omu[S * HID];             // [S][HID]
__device__ float g_ols[S * HID];             // [S][HID]
__device__ float g_kn[NH * S];               // [H][S] key norm terms

enum { M_PLAIN = 0, M_CAT = 1, M_CATEXP = 2, M_LOGIT = 3 };

// ---------------- generic SGEMM: C = A(MxK, row) * B(NxK, row)^T ----------------
// 128x128 tile, 8x8 per thread, 256 threads. Epilogue selected by MODE.
template <int MODE>
__global__ __launch_bounds__(256)
void gemm_nt(const float* __restrict__ Ag, const float* __restrict__ Bg,
             float* __restrict__ Cg,
             int M, int N, int K,
             long long sA, long long sB, long long sC,
             const float* __restrict__ knB, const float* __restrict__ tau,
             int catOff)
{
    const float* A = Ag + (size_t)blockIdx.z * (size_t)sA;
    const float* B = Bg + (size_t)blockIdx.z * (size_t)sB;
    float*       C = Cg + (size_t)blockIdx.z * (size_t)sC;

    __shared__ float As[BK][BM];
    __shared__ float Bs[BK][BN];

    const int tid = threadIdx.x;
    const int tx  = tid & 15;
    const int ty  = tid >> 4;

    const int lrow = tid >> 1;           // 0..127
    const int lcol = (tid & 1) << 2;     // 0 or 4

    const float* Ald = A + (size_t)(blockIdx.y * BM + lrow) * K + lcol;
    const float* Bld = B + (size_t)(blockIdx.x * BN + lrow) * K + lcol;

    float acc[8][8] = {};

    for (int k0 = 0; k0 < K; k0 += BK) {
        float4 av = *(const float4*)(Ald + k0);
        float4 bv = *(const float4*)(Bld + k0);
        As[lcol + 0][lrow] = av.x; As[lcol + 1][lrow] = av.y;
        As[lcol + 2][lrow] = av.z; As[lcol + 3][lrow] = av.w;
        Bs[lcol + 0][lrow] = bv.x; Bs[lcol + 1][lrow] = bv.y;
        Bs[lcol + 2][lrow] = bv.z; Bs[lcol + 3][lrow] = bv.w;
        __syncthreads();
#pragma unroll
        for (int kk = 0; kk < BK; kk++) {
            float4 a0 = *(const float4*)&As[kk][ty * 4];
            float4 a1 = *(const float4*)&As[kk][64 + ty * 4];
            float4 b0 = *(const float4*)&Bs[kk][tx * 4];
            float4 b1 = *(const float4*)&Bs[kk][64 + tx * 4];
            float ar[8] = {a0.x, a0.y, a0.z, a0.w, a1.x, a1.y, a1.z, a1.w};
            float br[8] = {b0.x, b0.y, b0.z, b0.w, b1.x, b1.y, b1.z, b1.w};
#pragma unroll
            for (int i = 0; i < 8; i++)
#pragma unroll
                for (int j = 0; j < 8; j++)
                    acc[i][j] = fmaf(ar[i], br[j], acc[i][j]);
        }
        __syncthreads();
    }

    float inv_den = 1.0f;
    const float* knh = nullptr;
    if (MODE == M_LOGIT) {
        inv_den = 1.0f / (fabsf(tau[0]) + 1e-6f);
        knh = knB + (size_t)blockIdx.z * N;
    }

#pragma unroll
    for (int i = 0; i < 8; i++) {
        int gr = blockIdx.y * BM + ((i < 4) ? ty * 4 + i : 64 + ty * 4 + (i - 4));
#pragma unroll
        for (int j = 0; j < 8; j++) {
            int gc = blockIdx.x * BN + ((j < 4) ? tx * 4 + j : 64 + tx * 4 + (j - 4));
            float v = acc[i][j];
            if (MODE == M_PLAIN) {
                C[(size_t)gr * N + gc] = v;
            } else if (MODE == M_CAT) {
                C[(((size_t)(gc >> 7)) * S + gr) * DC + (gc & 127) + catOff] = v;
            } else if (MODE == M_CATEXP) {
                C[(((size_t)(gc >> 7)) * S + gr) * DC + (gc & 127) + catOff] = expf(0.5f * v);
            } else { // M_LOGIT
                C[(size_t)gr * N + gc] = (2.0f * v - knh[gc]) * inv_den;
            }
        }
    }
}

// ---------------- PV GEMM: O = P(MxK, row) * V(KxN, row), split epilogue --------
__global__ __launch_bounds__(256)
void gemm_nn_split(const float* __restrict__ Pg, const float* __restrict__ Vg,
                   float* __restrict__ Omu, float* __restrict__ Ols,
                   int M, int N, int K)
{
    const int h = blockIdx.z;
    const float* A = Pg + (size_t)h * S * S;
    const float* B = Vg + (size_t)h * S * DC;

    __shared__ float As[BK][BM];
    __shared__ float Bs[BK][BN];

    const int tid = threadIdx.x;
    const int tx  = tid & 15;
    const int ty  = tid >> 4;

    const int larow = tid >> 1;
    const int lacol = (tid & 1) << 2;
    const int lbrow = tid >> 5;          // 0..7
    const int lbcol = (tid & 31) << 2;   // 0..124

    const float* Ald = A + (size_t)(blockIdx.y * BM + larow) * K + lacol;
    const float* Bld = B + (size_t)lbrow * N + blockIdx.x * BN + lbcol;

    float acc[8][8] = {};

    for (int k0 = 0; k0 < K; k0 += BK) {
        float4 av = *(const float4*)(Ald + k0);
        float4 bv = *(const float4*)(Bld + (size_t)k0 * N);
        As[lacol + 0][larow] = av.x; As[lacol + 1][larow] = av.y;
        As[lacol + 2][larow] = av.z; As[lacol + 3][larow] = av.w;
        *(float4*)&Bs[lbrow][lbcol] = bv;
        __syncthreads();
#pragma unroll
        for (int kk = 0; kk < BK; kk++) {
            float4 a0 = *(const float4*)&As[kk][ty * 4];
            float4 a1 = *(const float4*)&As[kk][64 + ty * 4];
            float4 b0 = *(const float4*)&Bs[kk][tx * 4];
            float4 b1 = *(const float4*)&Bs[kk][64 + tx * 4];
            float ar[8] = {a0.x, a0.y, a0.z, a0.w, a1.x, a1.y, a1.z, a1.w};
            float br[8] = {b0.x, b0.y, b0.z, b0.w, b1.x, b1.y, b1.z, b1.w};
#pragma unroll
            for (int i = 0; i < 8; i++)
#pragma unroll
                for (int j = 0; j < 8; j++)
                    acc[i][j] = fmaf(ar[i], br[j], acc[i][j]);
        }
        __syncthreads();
    }

#pragma unroll
    for (int i = 0; i < 8; i++) {
        int gr = blockIdx.y * BM + ((i < 4) ? ty * 4 + i : 64 + ty * 4 + (i - 4));
#pragma unroll
        for (int j = 0; j < 8; j++) {
            int gc = blockIdx.x * BN + ((j < 4) ? tx * 4 + j : 64 + tx * 4 + (j - 4));
            float v = acc[i][j];
            if (gc < HD) Omu[(size_t)gr * HID + h * HD + gc] = v;
            else         Ols[(size_t)gr * HID + h * HD + (gc - HD)] = v;
        }
    }
}

// ---------------- RoPE in-place on first 128 dims of qcat/kcat ------------------
__global__ void rope_kernel(float* __restrict__ qcat, float* __restrict__ kcat,
                            const float* __restrict__ cosp, const float* __restrict__ sinp)
{
    int idx = blockIdx.x * blockDim.x + threadIdx.x;   // NH*S*64 = 2^21 threads
    int d = idx & 63;
    int s = (idx >> 6) & (S - 1);
    int h = idx >> 17;
    float c1 = cosp[s * HD + d],      s1 = sinp[s * HD + d];
    float c2 = cosp[s * HD + d + 64], s2 = sinp[s * HD + d + 64];
    size_t base = ((size_t)h * S + s) * DC;
    float q1 = qcat[base + d], q2 = qcat[base + d + 64];
    qcat[base + d]      = q1 * c1 - q2 * s1;
    qcat[base + d + 64] = q2 * c2 + q1 * s2;
    float k1 = kcat[base + d], k2 = kcat[base + d + 64];
    kcat[base + d]      = k1 * c1 - k2 * s1;
    kcat[base + d + 64] = k2 * c2 + k1 * s2;
}

// ---------------- key norms: kn[h*S+s] = sum_{d<256} kcat[h][s][d]^2 ------------
__global__ void kn_kernel(const float* __restrict__ kcat, float* __restrict__ kn)
{
    int gwarp = (blockIdx.x * blockDim.x + threadIdx.x) >> 5;   // row index h*S+s
    int lane  = threadIdx.x & 31;
    const float4* p = (const float4*)(kcat + (size_t)gwarp * DC);
    float acc = 0.f;
#pragma unroll
    for (int i = lane; i < 64; i += 32) {
        float4 v = p[i];
        acc += v.x * v.x + v.y * v.y + v.z * v.z + v.w * v.w;
    }
#pragma unroll
    for (int o = 16; o; o >>= 1) acc += __shfl_xor_sync(0xffffffffu, acc, o);
    if (lane == 0) kn[gwarp] = acc;
}

// ---------------- row softmax on P (in place), one block per row ----------------
__global__ void softmax_rows(float* __restrict__ Pg)
{
    float* p = Pg + (size_t)blockIdx.x * S;
    int tid = threadIdx.x;           // 256 threads, 8 elems each
    float v[8];
    float m = -1e30f;
#pragma unroll
    for (int i = 0; i < 8; i++) { v[i] = p[tid + (i << 8)]; m = fmaxf(m, v[i]); }

    __shared__ float redm[8];
#pragma unroll
    for (int o = 16; o; o >>= 1) m = fmaxf(m, __shfl_xor_sync(0xffffffffu, m, o));
    if ((tid & 31) == 0) redm[tid >> 5] = m;
    __syncthreads();
    if (tid < 32) {
        float t = (tid < 8) ? redm[tid] : -1e30f;
#pragma unroll
        for (int o = 4; o; o >>= 1) t = fmaxf(t, __shfl_xor_sync(0xffffffffu, t, o));
        if (tid == 0) redm[0] = t;
    }
    __syncthreads();
    m = redm[0];

    float s = 0.f;
#pragma unroll
    for (int i = 0; i < 8; i++) { v[i] = __expf(v[i] - m); s += v[i]; }

    __shared__ float reds[8];
#pragma unroll
    for (int o = 16; o; o >>= 1) s += __shfl_xor_sync(0xffffffffu, s, o);
    if ((tid & 31) == 0) reds[tid >> 5] = s;
    __syncthreads();
    if (tid < 32) {
        float t = (tid < 8) ? reds[tid] : 0.f;
#pragma unroll
        for (int o = 4; o; o >>= 1) t += __shfl_xor_sync(0xffffffffu, t, o);
        if (tid == 0) reds[0] = t;
    }
    __syncthreads();
    float inv = 1.f / reds[0];
#pragma unroll
    for (int i = 0; i < 8; i++) p[tid + (i << 8)] = v[i] * inv;
}

// ---------------- launch -------------------------------------------------------
extern "C" void kernel_launch(void* const* d_in, const int* in_sizes, int n_in,
                              void* d_out, int out_size)
{
    const float* xmu  = (const float*)d_in[0];
    const float* xls  = (const float*)d_in[1];
    const float* cosp = (const float*)d_in[2];
    const float* sinp = (const float*)d_in[3];
    const float* Wqm  = (const float*)d_in[4];
    const float* Wkm  = (const float*)d_in[5];
    const float* Wvm  = (const float*)d_in[6];
    const float* Wom  = (const float*)d_in[7];
    const float* Wqs  = (const float*)d_in[8];
    const float* Wks  = (const float*)d_in[9];
    const float* Wvs  = (const float*)d_in[10];
    const float* Wos  = (const float*)d_in[11];
    const float* tau  = (const float*)d_in[12];
    float* out = (float*)d_out;

    float *qcat, *kcat, *vcat, *P, *omu, *ols, *kn;
    cudaGetSymbolAddress((void**)&qcat, g_qcat);
    cudaGetSymbolAddress((void**)&kcat, g_kcat);
    cudaGetSymbolAddress((void**)&vcat, g_vcat);
    cudaGetSymbolAddress((void**)&P,    g_P);
    cudaGetSymbolAddress((void**)&omu,  g_omu);
    cudaGetSymbolAddress((void**)&ols,  g_ols);
    cudaGetSymbolAddress((void**)&kn,   g_kn);

    dim3 blk(256);

    // 1) six input projections with fused scatter/exp epilogues
    dim3 gproj(HID / BN, S / BM, 1);
    gemm_nt<M_CAT   ><<<gproj, blk>>>(xmu, Wqm, qcat, S, HID, HID, 0, 0, 0, nullptr, nullptr, 0);
    gemm_nt<M_CAT   ><<<gproj, blk>>>(xmu, Wkm, kcat, S, HID, HID, 0, 0, 0, nullptr, nullptr, 0);
    gemm_nt<M_CAT   ><<<gproj, blk>>>(xmu, Wvm, vcat, S, HID, HID, 0, 0, 0, nullptr, nullptr, 0);
    gemm_nt<M_CATEXP><<<gproj, blk>>>(xls, Wqs, qcat, S, HID, HID, 0, 0, 0, nullptr, nullptr, HD);
    gemm_nt<M_CATEXP><<<gproj, blk>>>(xls, Wks, kcat, S, HID, HID, 0, 0, 0, nullptr, nullptr, HD);
    gemm_nt<M_CAT   ><<<gproj, blk>>>(xls, Wvs, vcat, S, HID, HID, 0, 0, 0, nullptr, nullptr, HD);

    // 2) RoPE on q_mu / k_mu halves
    rope_kernel<<<(NH * S * 64) / 256, 256>>>(qcat, kcat, cosp, sinp);

    // 3) key norm terms
    kn_kernel<<<(NH * S) / 8, 256>>>(kcat, kn);

    // 4) batched logit GEMM: P = (2*Qcat·Kcat^T - kn)/(|tau|+eps)
    dim3 glog(S / BN, S / BM, NH);
    gemm_nt<M_LOGIT><<<glog, blk>>>(qcat, kcat, P, S, S, DC,
                                    (long long)S * DC, (long long)S * DC,
                                    (long long)S * S, kn, tau, 0);

    // 5) softmax rows
    softmax_rows<<<NH * S, 256>>>(P);

    // 6) batched PV GEMM with split epilogue
    dim3 gpv(DC / BN, S / BM, NH);
    gemm_nn_split<<<gpv, blk>>>(P, vcat, omu, ols, S, DC, S);

    // 7) output projections
    dim3 gout(HID / BN, S / BM, 1);
    gemm_nt<M_PLAIN><<<gout, blk>>>(omu, Wom, out,                  S, HID, HID, 0, 0, 0, nullptr, nullptr, 0);
    gemm_nt<M_PLAIN><<<gout, blk>>>(ols, Wos, out + (size_t)S * HID, S, HID, HID, 0, 0, 0, nullptr, nullptr, 0);
}

// round 5
// speedup vs baseline: 2.5406x; 2.5406x over previous
#include <cuda_runtime.h>
#include <cuda_bf16.h>
#include <math.h>
#include <stdint.h>

typedef __nv_bfloat16 bf16;

#define Sn   2048
#define HIDn 2048
#define NHn  16
#define HDn  128
#define DCn  256

#define BMh  128
#define BNh  128
#define BKh  32          // bf16 k per block tile (64 bytes/row)
#define NTHR 256
#define ROWB 64          // bytes per smem row (BKh * 2)
#define TILE_B (BMh * ROWB)          // 8KB per operand tile
#define STAGE_B (2 * TILE_B)         // A + B per stage = 16KB

// ---------------- device globals (scratch) ----------------
static __device__ __align__(1024) bf16 g_Xmu_h[Sn*HIDn], g_Xmu_l[Sn*HIDn];
static __device__ __align__(1024) bf16 g_Xls_h[Sn*HIDn], g_Xls_l[Sn*HIDn];
static __device__ __align__(1024) bf16 g_W_h[8][HIDn*HIDn];
static __device__ __align__(1024) bf16 g_W_l[8][HIDn*HIDn];
static __device__ __align__(1024) float g_proj[6][(size_t)Sn*HIDn];
static __device__ __align__(1024) bf16 g_Q_h[(size_t)NHn*Sn*DCn], g_Q_l[(size_t)NHn*Sn*DCn];
static __device__ __align__(1024) bf16 g_K_h[(size_t)NHn*Sn*DCn], g_K_l[(size_t)NHn*Sn*DCn];
static __device__ __align__(1024) bf16 g_Vt_h[(size_t)NHn*DCn*Sn], g_Vt_l[(size_t)NHn*DCn*Sn];
static __device__ __align__(1024) float g_P[(size_t)NHn*Sn*Sn];
static __device__ __align__(1024) bf16 g_P_h[(size_t)NHn*Sn*Sn], g_P_l[(size_t)NHn*Sn*Sn];
static __device__ __align__(1024) float g_Om[(size_t)Sn*HIDn], g_Ol[(size_t)Sn*HIDn];
static __device__ __align__(1024) bf16 g_Om_h[Sn*HIDn], g_Om_l[Sn*HIDn];
static __device__ __align__(1024) bf16 g_Ol_h[Sn*HIDn], g_Ol_l[Sn*HIDn];
static __device__ float g_kn[NHn*Sn];

// ---------------- helpers ----------------
__device__ __forceinline__ uint32_t smem_u32(const void* p){
    uint32_t a;
    asm("{ .reg .u64 t; cvta.to.shared.u64 t, %1; cvt.u32.u64 %0, t; }" : "=r"(a) : "l"(p));
    return a;
}
__device__ __forceinline__ void cp16(uint32_t dst, const void* src){
    asm volatile("cp.async.cg.shared.global [%0], [%1], 16;" :: "r"(dst), "l"(src) : "memory");
}
#define CP_COMMIT() asm volatile("cp.async.commit_group;" ::: "memory")
#define CP_WAIT1()  asm volatile("cp.async.wait_group 1;" ::: "memory")

__device__ __forceinline__ void ldsm4(uint32_t& r0, uint32_t& r1, uint32_t& r2, uint32_t& r3, uint32_t addr){
    asm volatile("ldmatrix.sync.aligned.m8n8.x4.shared.b16 {%0,%1,%2,%3}, [%4];"
                 : "=r"(r0), "=r"(r1), "=r"(r2), "=r"(r3) : "r"(addr));
}
__device__ __forceinline__ void hmma(float* d, uint32_t a0, uint32_t a1, uint32_t a2, uint32_t a3,
                                     uint32_t b0, uint32_t b1){
    asm volatile("mma.sync.aligned.m16n8k16.row.col.f32.bf16.bf16.f32 "
                 "{%0,%1,%2,%3}, {%4,%5,%6,%7}, {%8,%9}, {%0,%1,%2,%3};"
                 : "+f"(d[0]), "+f"(d[1]), "+f"(d[2]), "+f"(d[3])
                 : "r"(a0), "r"(a1), "r"(a2), "r"(a3), "r"(b0), "r"(b1));
}
// smem chunk swizzle: 16B chunk c of row r stored at c ^ ((r>>1)&3)
__device__ __forceinline__ uint32_t sw_off(int row, int chunk){
    return (uint32_t)(row * ROWB + ((chunk ^ ((row >> 1) & 3)) << 4));
}

// ---------------- stage loader: A tile 128x32, B tile 128x32 (both K-major) ----
__device__ __forceinline__ void load_stage(uint32_t aAddr, uint32_t bAddr,
    const bf16* __restrict__ A, const bf16* __restrict__ B,
    int lda, int ldb, int koff, int tid)
{
#pragma unroll
    for (int i = 0; i < 2; i++){
        int id = tid + i*NTHR;          // 512 chunks
        int r = id >> 2, c = id & 3;
        cp16(aAddr + sw_off(r, c), A + (size_t)r*lda + koff + c*8);
    }
#pragma unroll
    for (int i = 0; i < 2; i++){
        int id = tid + i*NTHR;
        int r = id >> 2, c = id & 3;
        cp16(bAddr + sw_off(r, c), B + (size_t)r*ldb + koff + c*8);
    }
    CP_COMMIT();
}

enum { E_PLAIN = 0, E_LOGIT = 1, E_SPLITPV = 2 };

// ---------------- HMMA GEMM: C[M,N] = (Ah+Al)(Bh+Bl)^T via bf16x3 ----------------
// A: [M,K] row-major (K-major), B: [N,K] row-major (K-major). Batched over z.
template<int MODE>
__global__ void __launch_bounds__(NTHR, 2)
hm_gemm(const bf16* __restrict__ Ah, const bf16* __restrict__ Al,
        const bf16* __restrict__ Bh, const bf16* __restrict__ Bl,
        float* __restrict__ C, float* __restrict__ C2,
        int K, int lda, int ldb, int ldc,
        long long sA, long long sB, long long sC,
        const float* __restrict__ knArr, const float* __restrict__ tau)
{
    __shared__ __align__(128) char smem[2 * STAGE_B];   // 32KB
    const uint32_t sb = smem_u32(smem);
    const int tid  = threadIdx.x;
    const int wid  = tid >> 5;
    const int lane = tid & 31;
    const int wm = wid & 3;          // 4 warps along M (32 rows each)
    const int wn = wid >> 2;         // 2 warps along N (64 cols each)
    const int z = blockIdx.z;
    const int mbase = blockIdx.y * BMh, nbase = blockIdx.x * BNh;

    const bf16* pAh = Ah + (size_t)z*sA + (size_t)mbase*lda;
    const bf16* pAl = Al + (size_t)z*sA + (size_t)mbase*lda;
    const bf16* pBh = Bh + (size_t)z*sB + (size_t)nbase*ldb;
    const bf16* pBl = Bl + (size_t)z*sB + (size_t)nbase*ldb;

    const int kbn = K / BKh;
    const int NT  = 3 * kbn;

    uint32_t stA[2] = { sb,               sb + STAGE_B };
    uint32_t stB[2] = { sb + TILE_B,      sb + STAGE_B + TILE_B };

    float acc[2][8][4];
#pragma unroll
    for (int i = 0; i < 2; i++)
#pragma unroll
        for (int j = 0; j < 8; j++)
#pragma unroll
            for (int q = 0; q < 4; q++) acc[i][j][q] = 0.f;

    // ldmatrix per-lane base indices
    // A x4 (per m-tile): row = mt*16 + (l&7) + 8*((l>>3)&1), chunk = 2s + (l>>4)
    const int aRow = wm*32 + (lane & 7) + 8*((lane >> 3) & 1);
    const int aChk = lane >> 4;
    // B x4 (per n-pair): row = np*16 + (l&7) + 8*(l>>4), chunk = 2s + ((l>>3)&1)
    const int bRow = wn*64 + (lane & 7) + 8*(lane >> 4);
    const int bChk = (lane >> 3) & 1;

    // prologue
#pragma unroll
    for (int t = 0; t < 2; t++){
        int p = t / kbn, kb = t % kbn;
        load_stage(stA[t], stB[t], (p==1)?pAl:pAh, (p==2)?pBl:pBh, lda, ldb, kb*BKh, tid);
    }

    for (int t = 0; t < NT; t++){
        const int st = t & 1;
        CP_WAIT1();
        __syncthreads();

#pragma unroll
        for (int s = 0; s < 2; s++){
            uint32_t af[2][4];
#pragma unroll
            for (int mt = 0; mt < 2; mt++)
                ldsm4(af[mt][0], af[mt][1], af[mt][2], af[mt][3],
                      stA[st] + sw_off(aRow + mt*16, 2*s + aChk));
            uint32_t bf[4][4];
#pragma unroll
            for (int np = 0; np < 4; np++)
                ldsm4(bf[np][0], bf[np][1], bf[np][2], bf[np][3],
                      stB[st] + sw_off(bRow + np*16, 2*s + bChk));
#pragma unroll
            for (int mt = 0; mt < 2; mt++)
#pragma unroll
                for (int nt = 0; nt < 8; nt++){
                    const uint32_t* bb = bf[nt >> 1];
                    const int o = (nt & 1) * 2;
                    hmma(acc[mt][nt], af[mt][0], af[mt][1], af[mt][2], af[mt][3],
                         bb[o + 0], bb[o + 1]);
                }
        }
        __syncthreads();
        if (t + 2 < NT){
            int tn = t + 2;
            int p = tn / kbn, kb = tn % kbn;
            load_stage(stA[st], stB[st], (p==1)?pAl:pAh, (p==2)?pBl:pBh, lda, ldb, kb*BKh, tid);
        }
    }

    // epilogue
    float invden = 1.0f;
    const float* knz = nullptr;
    if (MODE == E_LOGIT){
        invden = 1.0f / (fabsf(tau[0]) + 1e-6f);
        knz = knArr + (size_t)z * Sn;
    }
    const int rr = lane >> 2;          // row within 8
    const int cc = (lane & 3) * 2;     // col pair within 8
#pragma unroll
    for (int mt = 0; mt < 2; mt++){
#pragma unroll
        for (int nt = 0; nt < 8; nt++){
#pragma unroll
            for (int half = 0; half < 2; half++){
                int grow = mbase + wm*32 + mt*16 + rr + half*8;
                int gcol = nbase + wn*64 + nt*8 + cc;
                float v0 = acc[mt][nt][half*2 + 0];
                float v1 = acc[mt][nt][half*2 + 1];
                if (MODE == E_LOGIT){
                    v0 = (2.0f*v0 - knz[gcol])   * invden;
                    v1 = (2.0f*v1 - knz[gcol+1]) * invden;
                }
                float2 vv = make_float2(v0, v1);
                if (MODE == E_SPLITPV){
                    float* dst = ((gcol < HDn) ? C : C2)
                               + (size_t)grow*ldc + (size_t)z*HDn + (gcol & (HDn-1));
                    *(float2*)dst = vv;
                } else {
                    float* dst = C + (size_t)z*sC + (size_t)grow*ldc + gcol;
                    *(float2*)dst = vv;
                }
            }
        }
    }
}

// ---------------- elementwise: fp32 -> bf16 hi/lo ----------------
__global__ void split_kernel(const float* __restrict__ in, bf16* __restrict__ h,
                             bf16* __restrict__ l, int n)
{
    int i = blockIdx.x*blockDim.x + threadIdx.x;
    if (i < n){
        float v = in[i];
        bf16 hh = __float2bfloat16(v);
        h[i] = hh;
        l[i] = __float2bfloat16(v - __bfloat162float(hh));
    }
}

// ---------------- Q/K transform: rope + exp + split + (kn) ----------------
__global__ void qk_transform(const float* __restrict__ mu, const float* __restrict__ ls,
                             const float* __restrict__ cosp, const float* __restrict__ sinp,
                             bf16* __restrict__ oh, bf16* __restrict__ ol,
                             float* __restrict__ kn)
{
    int s = blockIdx.x, h = blockIdx.y, d = threadIdx.x;   // 128 threads
    size_t ib = (size_t)s*HIDn + h*HDn;
    float m = mu[ib + d];
    float o = mu[ib + ((d < 64) ? d + 64 : d - 64)];
    float c = cosp[s*HDn + d], sv = sinp[s*HDn + d];
    float roped = (d < 64) ? (m*c - o*sv) : (m*c + o*sv);
    float sg = expf(0.5f * ls[ib + d]);
    size_t ob = ((size_t)h*Sn + s)*DCn;
    bf16 hh = __float2bfloat16(roped);
    oh[ob + d] = hh; ol[ob + d] = __float2bfloat16(roped - __bfloat162float(hh));
    bf16 hs = __float2bfloat16(sg);
    oh[ob + 128 + d] = hs; ol[ob + 128 + d] = __float2bfloat16(sg - __bfloat162float(hs));
    if (kn){
        float acc = roped*roped + sg*sg;
#pragma unroll
        for (int off = 16; off; off >>= 1) acc += __shfl_xor_sync(0xffffffffu, acc, off);
        __shared__ float red[4];
        if ((d & 31) == 0) red[d>>5] = acc;
        __syncthreads();
        if (d == 0) kn[(size_t)h*Sn + s] = red[0] + red[1] + red[2] + red[3];
    }
}

// ---------------- V transpose + split: Vt[h][d][s] ----------------
__global__ void v_transform(const float* __restrict__ vmu, const float* __restrict__ vls,
                            bf16* __restrict__ oh, bf16* __restrict__ ol)
{
    int i = blockIdx.x*blockDim.x + threadIdx.x;  // NH*DC*S = 2^23
    int s = i & (Sn-1);
    int d = (i >> 11) & (DCn-1);
    int h = i >> 19;
    float v = (d < HDn) ? vmu[(size_t)s*HIDn + h*HDn + d]
                        : vls[(size_t)s*HIDn + h*HDn + d - HDn];
    bf16 hh = __float2bfloat16(v);
    oh[i] = hh; ol[i] = __float2bfloat16(v - __bfloat162float(hh));
}

// ---------------- row softmax -> split bf16 hi/lo ----------------
__global__ void softmax_split(const float* __restrict__ Pg, bf16* __restrict__ Ph,
                              bf16* __restrict__ Pl)
{
    const float* p = Pg + (size_t)blockIdx.x * Sn;
    bf16* phr = Ph + (size_t)blockIdx.x * Sn;
    bf16* plr = Pl + (size_t)blockIdx.x * Sn;
    int tid = threadIdx.x;
    float v[8];
    float m = -1e30f;
#pragma unroll
    for (int i = 0; i < 8; i++){ v[i] = p[tid + (i<<8)]; m = fmaxf(m, v[i]); }
    __shared__ float redm[8], reds[8];
#pragma unroll
    for (int o = 16; o; o >>= 1) m = fmaxf(m, __shfl_xor_sync(0xffffffffu, m, o));
    if ((tid & 31) == 0) redm[tid>>5] = m;
    __syncthreads();
    if (tid < 32){
        float t = (tid < 8) ? redm[tid] : -1e30f;
#pragma unroll
        for (int o = 4; o; o >>= 1) t = fmaxf(t, __shfl_xor_sync(0xffffffffu, t, o));
        if (tid == 0) redm[0] = t;
    }
    __syncthreads();
    m = redm[0];
    float s = 0.f;
#pragma unroll
    for (int i = 0; i < 8; i++){ v[i] = __expf(v[i] - m); s += v[i]; }
#pragma unroll
    for (int o = 16; o; o >>= 1) s += __shfl_xor_sync(0xffffffffu, s, o);
    if ((tid & 31) == 0) reds[tid>>5] = s;
    __syncthreads();
    if (tid < 32){
        float t = (tid < 8) ? reds[tid] : 0.f;
#pragma unroll
        for (int o = 4; o; o >>= 1) t += __shfl_xor_sync(0xffffffffu, t, o);
        if (tid == 0) reds[0] = t;
    }
    __syncthreads();
    float inv = 1.f / reds[0];
#pragma unroll
    for (int i = 0; i < 8; i++){
        float pv = v[i] * inv;
        bf16 hh = __float2bfloat16(pv);
        phr[tid + (i<<8)] = hh;
        plr[tid + (i<<8)] = __float2bfloat16(pv - __bfloat162float(hh));
    }
}

// ---------------- launch ----------------
extern "C" void kernel_launch(void* const* d_in, const int* in_sizes, int n_in,
                              void* d_out, int out_size)
{
    const float* xmu  = (const float*)d_in[0];
    const float* xls  = (const float*)d_in[1];
    const float* cosp = (const float*)d_in[2];
    const float* sinp = (const float*)d_in[3];
    const float* Wsrc[8] = {
        (const float*)d_in[4], (const float*)d_in[5], (const float*)d_in[6], (const float*)d_in[7],
        (const float*)d_in[8], (const float*)d_in[9], (const float*)d_in[10], (const float*)d_in[11] };
    const float* tau = (const float*)d_in[12];
    float* out = (float*)d_out;

    bf16 *Xmu_h, *Xmu_l, *Xls_h, *Xls_l, *Wh, *Wl;
    bf16 *Qh, *Ql, *Kh, *Kl, *Vth, *Vtl, *Ph, *Pl;
    bf16 *Omh, *Oml, *Olh, *Oll;
    float *proj, *P, *Om, *Ol, *kn;
    cudaGetSymbolAddress((void**)&Xmu_h, g_Xmu_h); cudaGetSymbolAddress((void**)&Xmu_l, g_Xmu_l);
    cudaGetSymbolAddress((void**)&Xls_h, g_Xls_h); cudaGetSymbolAddress((void**)&Xls_l, g_Xls_l);
    cudaGetSymbolAddress((void**)&Wh, g_W_h);      cudaGetSymbolAddress((void**)&Wl, g_W_l);
    cudaGetSymbolAddress((void**)&proj, g_proj);
    cudaGetSymbolAddress((void**)&Qh, g_Q_h);  cudaGetSymbolAddress((void**)&Ql, g_Q_l);
    cudaGetSymbolAddress((void**)&Kh, g_K_h);  cudaGetSymbolAddress((void**)&Kl, g_K_l);
    cudaGetSymbolAddress((void**)&Vth, g_Vt_h); cudaGetSymbolAddress((void**)&Vtl, g_Vt_l);
    cudaGetSymbolAddress((void**)&P, g_P);
    cudaGetSymbolAddress((void**)&Ph, g_P_h);  cudaGetSymbolAddress((void**)&Pl, g_P_l);
    cudaGetSymbolAddress((void**)&Om, g_Om);   cudaGetSymbolAddress((void**)&Ol, g_Ol);
    cudaGetSymbolAddress((void**)&Omh, g_Om_h); cudaGetSymbolAddress((void**)&Oml, g_Om_l);
    cudaGetSymbolAddress((void**)&Olh, g_Ol_h); cudaGetSymbolAddress((void**)&Oll, g_Ol_l);
    cudaGetSymbolAddress((void**)&kn, g_kn);

    const int NE = HIDn*HIDn;
    dim3 eb(256);

    // 1) split inputs + weights to bf16 hi/lo
    split_kernel<<<(Sn*HIDn)/256, eb>>>(xmu, Xmu_h, Xmu_l, Sn*HIDn);
    split_kernel<<<(Sn*HIDn)/256, eb>>>(xls, Xls_h, Xls_l, Sn*HIDn);
    for (int w = 0; w < 8; w++)
        split_kernel<<<NE/256, eb>>>(Wsrc[w], Wh + (size_t)w*NE, Wl + (size_t)w*NE, NE);

    dim3 blk(NTHR);
    float* pq  = proj + 0*(size_t)Sn*HIDn;
    float* pqs = proj + 1*(size_t)Sn*HIDn;
    float* pk  = proj + 2*(size_t)Sn*HIDn;
    float* pks = proj + 3*(size_t)Sn*HIDn;
    float* pv  = proj + 4*(size_t)Sn*HIDn;
    float* pvs = proj + 5*(size_t)Sn*HIDn;

    // 2) six projections (NT, M=N=K=2048)
    dim3 gp(HIDn/BNh, Sn/BMh, 1);
    hm_gemm<E_PLAIN><<<gp, blk>>>(Xmu_h, Xmu_l, Wh + 0*(size_t)NE, Wl + 0*(size_t)NE, pq,  nullptr, HIDn, HIDn, HIDn, HIDn, 0,0,0, nullptr, nullptr);
    hm_gemm<E_PLAIN><<<gp, blk>>>(Xmu_h, Xmu_l, Wh + 1*(size_t)NE, Wl + 1*(size_t)NE, pk,  nullptr, HIDn, HIDn, HIDn, HIDn, 0,0,0, nullptr, nullptr);
    hm_gemm<E_PLAIN><<<gp, blk>>>(Xmu_h, Xmu_l, Wh + 2*(size_t)NE, Wl + 2*(size_t)NE, pv,  nullptr, HIDn, HIDn, HIDn, HIDn, 0,0,0, nullptr, nullptr);
    hm_gemm<E_PLAIN><<<gp, blk>>>(Xls_h, Xls_l, Wh + 4*(size_t)NE, Wl + 4*(size_t)NE, pqs, nullptr, HIDn, HIDn, HIDn, HIDn, 0,0,0, nullptr, nullptr);
    hm_gemm<E_PLAIN><<<gp, blk>>>(Xls_h, Xls_l, Wh + 5*(size_t)NE, Wl + 5*(size_t)NE, pks, nullptr, HIDn, HIDn, HIDn, HIDn, 0,0,0, nullptr, nullptr);
    hm_gemm<E_PLAIN><<<gp, blk>>>(Xls_h, Xls_l, Wh + 6*(size_t)NE, Wl + 6*(size_t)NE, pvs, nullptr, HIDn, HIDn, HIDn, HIDn, 0,0,0, nullptr, nullptr);

    // 3) Q/K transforms (+kn for K), V transpose-split
    qk_transform<<<dim3(Sn, NHn), 128>>>(pq, pqs, cosp, sinp, Qh, Ql, nullptr);
    qk_transform<<<dim3(Sn, NHn), 128>>>(pk, pks, cosp, sinp, Kh, Kl, kn);
    v_transform<<<((size_t)NHn*DCn*Sn)/256, eb>>>(pv, pvs, Vth, Vtl);

    // 4) logits: P = (2*Qcat.Kcat^T - kn)/(|tau|+eps), batched over heads
    dim3 gl(Sn/BNh, Sn/BMh, NHn);
    hm_gemm<E_LOGIT><<<gl, blk>>>(Qh, Ql, Kh, Kl, P, nullptr,
        DCn, DCn, DCn, Sn,
        (long long)Sn*DCn, (long long)Sn*DCn, (long long)Sn*Sn, kn, tau);

    // 5) softmax + split
    softmax_split<<<NHn*Sn, 256>>>(P, Ph, Pl);

    // 6) PV: O = P * Vt^T, split epilogue into Om/Ol (fp32, [S,HID])
    dim3 gv(DCn/BNh, Sn/BMh, NHn);
    hm_gemm<E_SPLITPV><<<gv, blk>>>(Ph, Pl, Vth, Vtl, Om, Ol,
        Sn, Sn, Sn, HIDn,
        (long long)Sn*Sn, (long long)DCn*Sn, 0, nullptr, nullptr);

    // 7) split O, output projections
    split_kernel<<<(Sn*HIDn)/256, eb>>>(Om, Omh, Oml, Sn*HIDn);
    split_kernel<<<(Sn*HIDn)/256, eb>>>(Ol, Olh, Oll, Sn*HIDn);
    hm_gemm<E_PLAIN><<<gp, blk>>>(Omh, Oml, Wh + 3*(size_t)NE, Wl + 3*(size_t)NE, out,                    nullptr, HIDn, HIDn, HIDn, HIDn, 0,0,0, nullptr, nullptr);
    hm_gemm<E_PLAIN><<<gp, blk>>>(Olh, Oll, Wh + 7*(size_t)NE, Wl + 7*(size_t)NE, out + (size_t)Sn*HIDn, nullptr, HIDn, HIDn, HIDn, HIDn, 0,0,0, nullptr, nullptr);
}

// round 6
// speedup vs baseline: 2.6470x; 1.0419x over previous
#include <cuda_runtime.h>
#include <cuda_bf16.h>
#include <math.h>
#include <stdint.h>

typedef __nv_bfloat16 bf16;

#define Sn   2048
#define HIDn 2048
#define NHn  16
#define HDn  128
#define DCn  256

#define BMh  128
#define BNh  128
#define BKh  32          // bf16 k per block tile (64 bytes/row)
#define NTHR 256
#define ROWB 64
#define TILE_B (BMh * ROWB)            // 8KB per operand tile
#define STAGE_B (4 * TILE_B)           // Ah, Al, Bh, Bl = 32KB per stage
#define NSTAGE 3
#define SMEM_DYN (NSTAGE * STAGE_B)    // 96KB

// ---------------- device globals (scratch) ----------------
static __device__ __align__(1024) bf16 g_Xmu_h[Sn*HIDn], g_Xmu_l[Sn*HIDn];
static __device__ __align__(1024) bf16 g_Xls_h[Sn*HIDn], g_Xls_l[Sn*HIDn];
static __device__ __align__(1024) bf16 g_W_h[8][HIDn*HIDn];
static __device__ __align__(1024) bf16 g_W_l[8][HIDn*HIDn];
static __device__ __align__(1024) float g_proj[6][(size_t)Sn*HIDn];
static __device__ __align__(1024) bf16 g_Q_h[(size_t)NHn*Sn*DCn], g_Q_l[(size_t)NHn*Sn*DCn];
static __device__ __align__(1024) bf16 g_K_h[(size_t)NHn*Sn*DCn], g_K_l[(size_t)NHn*Sn*DCn];
static __device__ __align__(1024) bf16 g_Vt_h[(size_t)NHn*DCn*Sn], g_Vt_l[(size_t)NHn*DCn*Sn];
static __device__ __align__(1024) float g_P[(size_t)NHn*Sn*Sn];
static __device__ __align__(1024) bf16 g_P_h[(size_t)NHn*Sn*Sn], g_P_l[(size_t)NHn*Sn*Sn];
static __device__ __align__(1024) bf16 g_Om_h[Sn*HIDn], g_Om_l[Sn*HIDn];
static __device__ __align__(1024) bf16 g_Ol_h[Sn*HIDn], g_Ol_l[Sn*HIDn];
static __device__ float g_kn[NHn*Sn];

// ---------------- helpers ----------------
__device__ __forceinline__ uint32_t smem_u32(const void* p){
    uint32_t a;
    asm("{ .reg .u64 t; cvta.to.shared.u64 t, %1; cvt.u32.u64 %0, t; }" : "=r"(a) : "l"(p));
    return a;
}
__device__ __forceinline__ void cp16(uint32_t dst, const void* src){
    asm volatile("cp.async.cg.shared.global [%0], [%1], 16;" :: "r"(dst), "l"(src) : "memory");
}
#define CP_COMMIT() asm volatile("cp.async.commit_group;" ::: "memory")
#define CP_WAIT1()  asm volatile("cp.async.wait_group 1;" ::: "memory")

__device__ __forceinline__ void ldsm4(uint32_t& r0, uint32_t& r1, uint32_t& r2, uint32_t& r3, uint32_t addr){
    asm volatile("ldmatrix.sync.aligned.m8n8.x4.shared.b16 {%0,%1,%2,%3}, [%4];"
                 : "=r"(r0), "=r"(r1), "=r"(r2), "=r"(r3) : "r"(addr));
}
__device__ __forceinline__ void hmma(float* d, uint32_t a0, uint32_t a1, uint32_t a2, uint32_t a3,
                                     uint32_t b0, uint32_t b1){
    asm volatile("mma.sync.aligned.m16n8k16.row.col.f32.bf16.bf16.f32 "
                 "{%0,%1,%2,%3}, {%4,%5,%6,%7}, {%8,%9}, {%0,%1,%2,%3};"
                 : "+f"(d[0]), "+f"(d[1]), "+f"(d[2]), "+f"(d[3])
                 : "r"(a0), "r"(a1), "r"(a2), "r"(a3), "r"(b0), "r"(b1));
}
__device__ __forceinline__ uint32_t sw_off(int row, int chunk){
    return (uint32_t)(row * ROWB + ((chunk ^ ((row >> 1) & 3)) << 4));
}

// ---------------- 4-tile stage loader: Ah, Al (128x32), Bh, Bl (128x32) --------
__device__ __forceinline__ void load_stage4(uint32_t st,
    const bf16* __restrict__ Ah, const bf16* __restrict__ Al,
    const bf16* __restrict__ Bh, const bf16* __restrict__ Bl,
    int lda, int ldb, int koff, int tid)
{
#pragma unroll
    for (int i = 0; i < 8; i++){
        const int tile = i >> 1;                 // compile-time per unrolled i
        const int id = tid + i*NTHR;             // 0..2047
        const int r = (id >> 2) & 127;
        const int c = id & 3;
        const bf16* base = (tile==0) ? Ah : (tile==1) ? Al : (tile==2) ? Bh : Bl;
        const int ld = (tile < 2) ? lda : ldb;
        cp16(st + tile*TILE_B + sw_off(r, c), base + (size_t)r*ld + koff + c*8);
    }
    CP_COMMIT();
}

enum { E_PLAIN = 0, E_LOGIT = 1, E_SPLITPV = 2 };

// ---------------- HMMA GEMM: C[M,N] = (Ah+Al)(Bh+Bl)^T via bf16x3 ----------------
template<int MODE>
__global__ void __launch_bounds__(NTHR, 2)
hm_gemm(const bf16* __restrict__ Ah, const bf16* __restrict__ Al,
        const bf16* __restrict__ Bh, const bf16* __restrict__ Bl,
        float* __restrict__ C,
        bf16* __restrict__ OH, bf16* __restrict__ OL,
        bf16* __restrict__ OH2, bf16* __restrict__ OL2,
        int K, int lda, int ldb, int ldc,
        long long sA, long long sB, long long sC,
        const float* __restrict__ knArr, const float* __restrict__ tau)
{
    extern __shared__ __align__(128) char smem[];
    const uint32_t sb = smem_u32(smem);
    const int tid  = threadIdx.x;
    const int wid  = tid >> 5;
    const int lane = tid & 31;
    const int wm = wid & 3;
    const int wn = wid >> 2;
    const int z = blockIdx.z;
    const int mbase = blockIdx.y * BMh, nbase = blockIdx.x * BNh;

    const bf16* pAh = Ah + (size_t)z*sA + (size_t)mbase*lda;
    const bf16* pAl = Al + (size_t)z*sA + (size_t)mbase*lda;
    const bf16* pBh = Bh + (size_t)z*sB + (size_t)nbase*ldb;
    const bf16* pBl = Bl + (size_t)z*sB + (size_t)nbase*ldb;

    const int kbn = K / BKh;

    float acc[2][8][4];
#pragma unroll
    for (int i = 0; i < 2; i++)
#pragma unroll
        for (int j = 0; j < 8; j++)
#pragma unroll
            for (int q = 0; q < 4; q++) acc[i][j][q] = 0.f;

    const int aRow = wm*32 + (lane & 7) + 8*((lane >> 3) & 1);
    const int aChk = lane >> 4;
    const int bRow = wn*64 + (lane & 7) + 8*(lane >> 4);
    const int bChk = (lane >> 3) & 1;

    // prologue: stages 0,1
    load_stage4(sb + 0*STAGE_B, pAh, pAl, pBh, pBl, lda, ldb, 0,   tid);
    load_stage4(sb + 1*STAGE_B, pAh, pAl, pBh, pBl, lda, ldb, BKh, tid);

    int stidx = 0;
    for (int kb = 0; kb < kbn; kb++){
        const uint32_t st = sb + stidx*STAGE_B;
        CP_WAIT1();
        __syncthreads();

#pragma unroll
        for (int p = 0; p < 3; p++){
            const uint32_t aT = st + ((p == 1) ? TILE_B : 0);
            const uint32_t bT = st + 2*TILE_B + ((p == 2) ? TILE_B : 0);
#pragma unroll
            for (int s = 0; s < 2; s++){
                uint32_t af[2][4];
#pragma unroll
                for (int mt = 0; mt < 2; mt++)
                    ldsm4(af[mt][0], af[mt][1], af[mt][2], af[mt][3],
                          aT + sw_off(aRow + mt*16, 2*s + aChk));
                uint32_t bfr[4][4];
#pragma unroll
                for (int np = 0; np < 4; np++)
                    ldsm4(bfr[np][0], bfr[np][1], bfr[np][2], bfr[np][3],
                          bT + sw_off(bRow + np*16, 2*s + bChk));
#pragma unroll
                for (int mt = 0; mt < 2; mt++)
#pragma unroll
                    for (int nt = 0; nt < 8; nt++){
                        const uint32_t* bb = bfr[nt >> 1];
                        const int o = (nt & 1) * 2;
                        hmma(acc[mt][nt], af[mt][0], af[mt][1], af[mt][2], af[mt][3],
                             bb[o + 0], bb[o + 1]);
                    }
            }
        }
        __syncthreads();
        if (kb + 2 < kbn){
            const int nidx = (stidx + 2 >= NSTAGE) ? stidx + 2 - NSTAGE : stidx + 2;
            load_stage4(sb + nidx*STAGE_B, pAh, pAl, pBh, pBl, lda, ldb, (kb+2)*BKh, tid);
        }
        stidx = (stidx + 1 == NSTAGE) ? 0 : stidx + 1;
    }

    // epilogue
    float invden = 1.0f;
    const float* knz = nullptr;
    if (MODE == E_LOGIT){
        invden = 1.0f / (fabsf(tau[0]) + 1e-6f);
        knz = knArr + (size_t)z * Sn;
    }
    const int rr = lane >> 2;
    const int cc = (lane & 3) * 2;
#pragma unroll
    for (int mt = 0; mt < 2; mt++){
#pragma unroll
        for (int nt = 0; nt < 8; nt++){
#pragma unroll
            for (int half = 0; half < 2; half++){
                int grow = mbase + wm*32 + mt*16 + rr + half*8;
                int gcol = nbase + wn*64 + nt*8 + cc;
                float v0 = acc[mt][nt][half*2 + 0];
                float v1 = acc[mt][nt][half*2 + 1];
                if (MODE == E_LOGIT){
                    v0 = (2.0f*v0 - knz[gcol])   * invden;
                    v1 = (2.0f*v1 - knz[gcol+1]) * invden;
                }
                if (MODE == E_SPLITPV){
                    // write bf16 hi/lo pairs directly (mu if nbase<HD, else ls)
                    bf16* dh = (nbase < HDn) ? OH : OH2;
                    bf16* dl = (nbase < HDn) ? OL : OL2;
                    size_t off = (size_t)grow*HIDn + (size_t)z*HDn + (gcol & (HDn-1));
                    bf16 h0 = __float2bfloat16(v0);
                    bf16 h1 = __float2bfloat16(v1);
                    __nv_bfloat162 hh; hh.x = h0; hh.y = h1;
                    __nv_bfloat162 ll;
                    ll.x = __float2bfloat16(v0 - __bfloat162float(h0));
                    ll.y = __float2bfloat16(v1 - __bfloat162float(h1));
                    *(__nv_bfloat162*)(dh + off) = hh;
                    *(__nv_bfloat162*)(dl + off) = ll;
                } else {
                    float2 vv = make_float2(v0, v1);
                    float* dst = C + (size_t)z*sC + (size_t)grow*ldc + gcol;
                    *(float2*)dst = vv;
                }
            }
        }
    }
}

// ---------------- elementwise: fp32 -> bf16 hi/lo ----------------
__global__ void split_kernel(const float* __restrict__ in, bf16* __restrict__ h,
                             bf16* __restrict__ l, int n)
{
    int i = blockIdx.x*blockDim.x + threadIdx.x;
    if (i < n){
        float v = in[i];
        bf16 hh = __float2bfloat16(v);
        h[i] = hh;
        l[i] = __float2bfloat16(v - __bfloat162float(hh));
    }
}

// batched weight split: 8 matrices in one launch
__global__ void split8_kernel(const float* __restrict__ w0, const float* __restrict__ w1,
                              const float* __restrict__ w2, const float* __restrict__ w3,
                              const float* __restrict__ w4, const float* __restrict__ w5,
                              const float* __restrict__ w6, const float* __restrict__ w7,
                              bf16* __restrict__ h, bf16* __restrict__ l)
{
    const int w = blockIdx.y;
    const float* src;
    switch (w){
        case 0: src = w0; break; case 1: src = w1; break;
        case 2: src = w2; break; case 3: src = w3; break;
        case 4: src = w4; break; case 5: src = w5; break;
        case 6: src = w6; break; default: src = w7; break;
    }
    size_t i = (size_t)blockIdx.x*blockDim.x + threadIdx.x;
    float v = src[i];
    bf16 hh = __float2bfloat16(v);
    size_t o = (size_t)w*HIDn*HIDn + i;
    h[o] = hh;
    l[o] = __float2bfloat16(v - __bfloat162float(hh));
}

// ---------------- Q/K transform: rope + exp + split + (kn) ----------------
__global__ void qk_transform(const float* __restrict__ mu, const float* __restrict__ ls,
                             const float* __restrict__ cosp, const float* __restrict__ sinp,
                             bf16* __restrict__ oh, bf16* __restrict__ ol,
                             float* __restrict__ kn)
{
    int s = blockIdx.x, h = blockIdx.y, d = threadIdx.x;   // 128 threads
    size_t ib = (size_t)s*HIDn + h*HDn;
    float m = mu[ib + d];
    float o = mu[ib + ((d < 64) ? d + 64 : d - 64)];
    float c = cosp[s*HDn + d], sv = sinp[s*HDn + d];
    float roped = (d < 64) ? (m*c - o*sv) : (m*c + o*sv);
    float sg = expf(0.5f * ls[ib + d]);
    size_t ob = ((size_t)h*Sn + s)*DCn;
    bf16 hh = __float2bfloat16(roped);
    oh[ob + d] = hh; ol[ob + d] = __float2bfloat16(roped - __bfloat162float(hh));
    bf16 hs = __float2bfloat16(sg);
    oh[ob + 128 + d] = hs; ol[ob + 128 + d] = __float2bfloat16(sg - __bfloat162float(hs));
    if (kn){
        float acc = roped*roped + sg*sg;
#pragma unroll
        for (int off = 16; off; off >>= 1) acc += __shfl_xor_sync(0xffffffffu, acc, off);
        __shared__ float red[4];
        if ((d & 31) == 0) red[d>>5] = acc;
        __syncthreads();
        if (d == 0) kn[(size_t)h*Sn + s] = red[0] + red[1] + red[2] + red[3];
    }
}

// ---------------- V transpose + split: Vt[h][d][s] ----------------
__global__ void v_transform(const float* __restrict__ vmu, const float* __restrict__ vls,
                            bf16* __restrict__ oh, bf16* __restrict__ ol)
{
    int i = blockIdx.x*blockDim.x + threadIdx.x;  // NH*DC*S = 2^23
    int s = i & (Sn-1);
    int d = (i >> 11) & (DCn-1);
    int h = i >> 19;
    float v = (d < HDn) ? vmu[(size_t)s*HIDn + h*HDn + d]
                        : vls[(size_t)s*HIDn + h*HDn + d - HDn];
    bf16 hh = __float2bfloat16(v);
    oh[i] = hh; ol[i] = __float2bfloat16(v - __bfloat162float(hh));
}

// ---------------- row softmax -> split bf16 hi/lo ----------------
__global__ void softmax_split(const float* __restrict__ Pg, bf16* __restrict__ Ph,
                              bf16* __restrict__ Pl)
{
    const float* p = Pg + (size_t)blockIdx.x * Sn;
    bf16* phr = Ph + (size_t)blockIdx.x * Sn;
    bf16* plr = Pl + (size_t)blockIdx.x * Sn;
    int tid = threadIdx.x;
    float v[8];
    float m = -1e30f;
#pragma unroll
    for (int i = 0; i < 8; i++){ v[i] = p[tid + (i<<8)]; m = fmaxf(m, v[i]); }
    __shared__ float redm[8], reds[8];
#pragma unroll
    for (int o = 16; o; o >>= 1) m = fmaxf(m, __shfl_xor_sync(0xffffffffu, m, o));
    if ((tid & 31) == 0) redm[tid>>5] = m;
    __syncthreads();
    if (tid < 32){
        float t = (tid < 8) ? redm[tid] : -1e30f;
#pragma unroll
        for (int o = 4; o; o >>= 1) t = fmaxf(t, __shfl_xor_sync(0xffffffffu, t, o));
        if (tid == 0) redm[0] = t;
    }
    __syncthreads();
    m = redm[0];
    float s = 0.f;
#pragma unroll
    for (int i = 0; i < 8; i++){ v[i] = __expf(v[i] - m); s += v[i]; }
#pragma unroll
    for (int o = 16; o; o >>= 1) s += __shfl_xor_sync(0xffffffffu, s, o);
    if ((tid & 31) == 0) reds[tid>>5] = s;
    __syncthreads();
    if (tid < 32){
        float t = (tid < 8) ? reds[tid] : 0.f;
#pragma unroll
        for (int o = 4; o; o >>= 1) t += __shfl_xor_sync(0xffffffffu, t, o);
        if (tid == 0) reds[0] = t;
    }
    __syncthreads();
    float inv = 1.f / reds[0];
#pragma unroll
    for (int i = 0; i < 8; i++){
        float pv = v[i] * inv;
        bf16 hh = __float2bfloat16(pv);
        phr[tid + (i<<8)] = hh;
        plr[tid + (i<<8)] = __float2bfloat16(pv - __bfloat162float(hh));
    }
}

// ---------------- launch ----------------
extern "C" void kernel_launch(void* const* d_in, const int* in_sizes, int n_in,
                              void* d_out, int out_size)
{
    const float* xmu  = (const float*)d_in[0];
    const float* xls  = (const float*)d_in[1];
    const float* cosp = (const float*)d_in[2];
    const float* sinp = (const float*)d_in[3];
    const float* tau  = (const float*)d_in[12];
    float* out = (float*)d_out;

    bf16 *Xmu_h, *Xmu_l, *Xls_h, *Xls_l, *Wh, *Wl;
    bf16 *Qh, *Ql, *Kh, *Kl, *Vth, *Vtl, *Ph, *Pl;
    bf16 *Omh, *Oml, *Olh, *Oll;
    float *proj, *P, *kn;
    cudaGetSymbolAddress((void**)&Xmu_h, g_Xmu_h); cudaGetSymbolAddress((void**)&Xmu_l, g_Xmu_l);
    cudaGetSymbolAddress((void**)&Xls_h, g_Xls_h); cudaGetSymbolAddress((void**)&Xls_l, g_Xls_l);
    cudaGetSymbolAddress((void**)&Wh, g_W_h);      cudaGetSymbolAddress((void**)&Wl, g_W_l);
    cudaGetSymbolAddress((void**)&proj, g_proj);
    cudaGetSymbolAddress((void**)&Qh, g_Q_h);  cudaGetSymbolAddress((void**)&Ql, g_Q_l);
    cudaGetSymbolAddress((void**)&Kh, g_K_h);  cudaGetSymbolAddress((void**)&Kl, g_K_l);
    cudaGetSymbolAddress((void**)&Vth, g_Vt_h); cudaGetSymbolAddress((void**)&Vtl, g_Vt_l);
    cudaGetSymbolAddress((void**)&P, g_P);
    cudaGetSymbolAddress((void**)&Ph, g_P_h);  cudaGetSymbolAddress((void**)&Pl, g_P_l);
    cudaGetSymbolAddress((void**)&Omh, g_Om_h); cudaGetSymbolAddress((void**)&Oml, g_Om_l);
    cudaGetSymbolAddress((void**)&Olh, g_Ol_h); cudaGetSymbolAddress((void**)&Oll, g_Ol_l);
    cudaGetSymbolAddress((void**)&kn, g_kn);

    cudaFuncSetAttribute(hm_gemm<E_PLAIN>,  cudaFuncAttributeMaxDynamicSharedMemorySize, SMEM_DYN);
    cudaFuncSetAttribute(hm_gemm<E_LOGIT>,  cudaFuncAttributeMaxDynamicSharedMemorySize, SMEM_DYN);
    cudaFuncSetAttribute(hm_gemm<E_SPLITPV>,cudaFuncAttributeMaxDynamicSharedMemorySize, SMEM_DYN);

    const int NE = HIDn*HIDn;
    dim3 eb(256);

    // 1) split inputs + weights
    split_kernel<<<(Sn*HIDn)/256, eb>>>(xmu, Xmu_h, Xmu_l, Sn*HIDn);
    split_kernel<<<(Sn*HIDn)/256, eb>>>(xls, Xls_h, Xls_l, Sn*HIDn);
    split8_kernel<<<dim3(NE/256, 8), eb>>>(
        (const float*)d_in[4], (const float*)d_in[5], (const float*)d_in[6], (const float*)d_in[7],
        (const float*)d_in[8], (const float*)d_in[9], (const float*)d_in[10], (const float*)d_in[11],
        Wh, Wl);

    dim3 blk(NTHR);
    size_t shm = SMEM_DYN;
    float* pq  = proj + 0*(size_t)Sn*HIDn;
    float* pqs = proj + 1*(size_t)Sn*HIDn;
    float* pk  = proj + 2*(size_t)Sn*HIDn;
    float* pks = proj + 3*(size_t)Sn*HIDn;
    float* pv  = proj + 4*(size_t)Sn*HIDn;
    float* pvs = proj + 5*(size_t)Sn*HIDn;

    // 2) six projections
    dim3 gp(HIDn/BNh, Sn/BMh, 1);
    hm_gemm<E_PLAIN><<<gp, blk, shm>>>(Xmu_h, Xmu_l, Wh + 0*(size_t)NE, Wl + 0*(size_t)NE, pq,  nullptr,nullptr,nullptr,nullptr, HIDn, HIDn, HIDn, HIDn, 0,0,0, nullptr, nullptr);
    hm_gemm<E_PLAIN><<<gp, blk, shm>>>(Xmu_h, Xmu_l, Wh + 1*(size_t)NE, Wl + 1*(size_t)NE, pk,  nullptr,nullptr,nullptr,nullptr, HIDn, HIDn, HIDn, HIDn, 0,0,0, nullptr, nullptr);
    hm_gemm<E_PLAIN><<<gp, blk, shm>>>(Xmu_h, Xmu_l, Wh + 2*(size_t)NE, Wl + 2*(size_t)NE, pv,  nullptr,nullptr,nullptr,nullptr, HIDn, HIDn, HIDn, HIDn, 0,0,0, nullptr, nullptr);
    hm_gemm<E_PLAIN><<<gp, blk, shm>>>(Xls_h, Xls_l, Wh + 4*(size_t)NE, Wl + 4*(size_t)NE, pqs, nullptr,nullptr,nullptr,nullptr, HIDn, HIDn, HIDn, HIDn, 0,0,0, nullptr, nullptr);
    hm_gemm<E_PLAIN><<<gp, blk, shm>>>(Xls_h, Xls_l, Wh + 5*(size_t)NE, Wl + 5*(size_t)NE, pks, nullptr,nullptr,nullptr,nullptr, HIDn, HIDn, HIDn, HIDn, 0,0,0, nullptr, nullptr);
    hm_gemm<E_PLAIN><<<gp, blk, shm>>>(Xls_h, Xls_l, Wh + 6*(size_t)NE, Wl + 6*(size_t)NE, pvs, nullptr,nullptr,nullptr,nullptr, HIDn, HIDn, HIDn, HIDn, 0,0,0, nullptr, nullptr);

    // 3) transforms
    qk_transform<<<dim3(Sn, NHn), 128>>>(pq, pqs, cosp, sinp, Qh, Ql, nullptr);
    qk_transform<<<dim3(Sn, NHn), 128>>>(pk, pks, cosp, sinp, Kh, Kl, kn);
    v_transform<<<((size_t)NHn*DCn*Sn)/256, eb>>>(pv, pvs, Vth, Vtl);

    // 4) logits
    dim3 gl(Sn/BNh, Sn/BMh, NHn);
    hm_gemm<E_LOGIT><<<gl, blk, shm>>>(Qh, Ql, Kh, Kl, P, nullptr,nullptr,nullptr,nullptr,
        DCn, DCn, DCn, Sn,
        (long long)Sn*DCn, (long long)Sn*DCn, (long long)Sn*Sn, kn, tau);

    // 5) softmax + split
    softmax_split<<<NHn*Sn, 256>>>(P, Ph, Pl);

    // 6) PV with fused bf16 hi/lo split epilogue
    dim3 gv(DCn/BNh, Sn/BMh, NHn);
    hm_gemm<E_SPLITPV><<<gv, blk, shm>>>(Ph, Pl, Vth, Vtl, nullptr, Omh, Oml, Olh, Oll,
        Sn, Sn, Sn, HIDn,
        (long long)Sn*Sn, (long long)DCn*Sn, 0, nullptr, nullptr);

    // 7) output projections (consume fused hi/lo directly)
    dim3 gp2(HIDn/BNh, Sn/BMh, 1);
    hm_gemm<E_PLAIN><<<gp2, blk, shm>>>(Omh, Oml, Wh + 3*(size_t)NE, Wl + 3*(size_t)NE, out,                    nullptr,nullptr,nullptr,nullptr, HIDn, HIDn, HIDn, HIDn, 0,0,0, nullptr, nullptr);
    hm_gemm<E_PLAIN><<<gp2, blk, shm>>>(Olh, Oll, Wh + 7*(size_t)NE, Wl + 7*(size_t)NE, out + (size_t)Sn*HIDn, nullptr,nullptr,nullptr,nullptr, HIDn, HIDn, HIDn, HIDn, 0,0,0, nullptr, nullptr);
}

// round 7
// speedup vs baseline: 2.9251x; 1.1051x over previous
#include <cuda_runtime.h>
#include <cuda_bf16.h>
#include <math.h>
#include <stdint.h>

typedef __nv_bfloat16 bf16;

#define Sn   2048
#define HIDn 2048
#define NHn  16
#define HDn  128
#define DCn  256

#define BMh  128
#define BNh  128
#define BKh  32
#define NTHR 256
#define ROWB 64
#define TILE_B (BMh * ROWB)            // 8KB per operand tile
#define STAGE_B (4 * TILE_B)           // Ah, Al, Bh, Bl = 32KB per stage
#define NSTAGE 3
#define SMEM_DYN (NSTAGE * STAGE_B)    // 96KB

// ---------------- device globals (scratch) ----------------
static __device__ __align__(1024) bf16 g_Xmu_h[Sn*HIDn], g_Xmu_l[Sn*HIDn];
static __device__ __align__(1024) bf16 g_Xls_h[Sn*HIDn], g_Xls_l[Sn*HIDn];
static __device__ __align__(1024) bf16 g_W_h[8][HIDn*HIDn];
static __device__ __align__(1024) bf16 g_W_l[8][HIDn*HIDn];
static __device__ __align__(1024) float g_proj[6][(size_t)Sn*HIDn];
static __device__ __align__(1024) bf16 g_Q_h[(size_t)NHn*Sn*DCn], g_Q_l[(size_t)NHn*Sn*DCn];
static __device__ __align__(1024) bf16 g_K_h[(size_t)NHn*Sn*DCn], g_K_l[(size_t)NHn*Sn*DCn];
static __device__ __align__(1024) bf16 g_Vt_h[(size_t)NHn*DCn*Sn], g_Vt_l[(size_t)NHn*DCn*Sn];
static __device__ __align__(1024) float g_P[(size_t)NHn*Sn*Sn];
static __device__ __align__(1024) bf16 g_P_h[(size_t)NHn*Sn*Sn], g_P_l[(size_t)NHn*Sn*Sn];
static __device__ __align__(1024) bf16 g_Om_h[Sn*HIDn], g_Om_l[Sn*HIDn];
static __device__ __align__(1024) bf16 g_Ol_h[Sn*HIDn], g_Ol_l[Sn*HIDn];
static __device__ float g_kn[NHn*Sn];

// ---------------- helpers ----------------
__device__ __forceinline__ uint32_t smem_u32(const void* p){
    uint32_t a;
    asm("{ .reg .u64 t; cvta.to.shared.u64 t, %1; cvt.u32.u64 %0, t; }" : "=r"(a) : "l"(p));
    return a;
}
__device__ __forceinline__ void cp16(uint32_t dst, const void* src){
    asm volatile("cp.async.cg.shared.global [%0], [%1], 16;" :: "r"(dst), "l"(src) : "memory");
}
#define CP_COMMIT() asm volatile("cp.async.commit_group;" ::: "memory")
#define CP_WAIT1()  asm volatile("cp.async.wait_group 1;" ::: "memory")

__device__ __forceinline__ void ldsm4(uint32_t* r, uint32_t addr){
    asm volatile("ldmatrix.sync.aligned.m8n8.x4.shared.b16 {%0,%1,%2,%3}, [%4];"
                 : "=r"(r[0]), "=r"(r[1]), "=r"(r[2]), "=r"(r[3]) : "r"(addr));
}
__device__ __forceinline__ void hmma(float* d, const uint32_t* a, uint32_t b0, uint32_t b1){
    asm volatile("mma.sync.aligned.m16n8k16.row.col.f32.bf16.bf16.f32 "
                 "{%0,%1,%2,%3}, {%4,%5,%6,%7}, {%8,%9}, {%0,%1,%2,%3};"
                 : "+f"(d[0]), "+f"(d[1]), "+f"(d[2]), "+f"(d[3])
                 : "r"(a[0]), "r"(a[1]), "r"(a[2]), "r"(a[3]), "r"(b0), "r"(b1));
}
__device__ __forceinline__ uint32_t sw_off(int row, int chunk){
    return (uint32_t)(row * ROWB + ((chunk ^ ((row >> 1) & 3)) << 4));
}

// ---------------- 4-tile stage loader ----------------
__device__ __forceinline__ void load_stage4(uint32_t st,
    const bf16* __restrict__ Ah, const bf16* __restrict__ Al,
    const bf16* __restrict__ Bh, const bf16* __restrict__ Bl,
    int lda, int ldb, int koff, int tid)
{
#pragma unroll
    for (int i = 0; i < 8; i++){
        const int tile = i >> 1;
        const int id = tid + i*NTHR;
        const int r = (id >> 2) & 127;
        const int c = id & 3;
        const bf16* base = (tile==0) ? Ah : (tile==1) ? Al : (tile==2) ? Bh : Bl;
        const int ld = (tile < 2) ? lda : ldb;
        cp16(st + tile*TILE_B + sw_off(r, c), base + (size_t)r*ld + koff + c*8);
    }
    CP_COMMIT();
}

enum { E_PLAIN = 0, E_LOGIT = 1, E_SPLITPV = 2 };

// ---------------- HMMA GEMM: C[M,N] = (Ah+Al)(Bh+Bl)^T via bf16x3 ----------------
template<int MODE>
__global__ void __launch_bounds__(NTHR, 2)
hm_gemm(const bf16* __restrict__ Ah, const bf16* __restrict__ Al,
        const bf16* __restrict__ Bh, const bf16* __restrict__ Bl,
        float* __restrict__ C,
        bf16* __restrict__ OH, bf16* __restrict__ OL,
        bf16* __restrict__ OH2, bf16* __restrict__ OL2,
        int K, int lda, int ldb, int ldc,
        long long sA, long long sB, long long sC,
        const float* __restrict__ knArr, const float* __restrict__ tau)
{
    extern __shared__ __align__(128) char smem[];
    const uint32_t sb = smem_u32(smem);
    const int tid  = threadIdx.x;
    const int wid  = tid >> 5;
    const int lane = tid & 31;
    const int wm = wid & 3;
    const int wn = wid >> 2;
    const int z = blockIdx.z;
    const int mbase = blockIdx.y * BMh, nbase = blockIdx.x * BNh;

    const bf16* pAh = Ah + (size_t)z*sA + (size_t)mbase*lda;
    const bf16* pAl = Al + (size_t)z*sA + (size_t)mbase*lda;
    const bf16* pBh = Bh + (size_t)z*sB + (size_t)nbase*ldb;
    const bf16* pBl = Bl + (size_t)z*sB + (size_t)nbase*ldb;

    const int kbn = K / BKh;

    float acc[2][8][4];
#pragma unroll
    for (int i = 0; i < 2; i++)
#pragma unroll
        for (int j = 0; j < 8; j++)
#pragma unroll
            for (int q = 0; q < 4; q++) acc[i][j][q] = 0.f;

    const int aRow = wm*32 + (lane & 7) + 8*((lane >> 3) & 1);
    const int aChk = lane >> 4;
    const int bRow = wn*64 + (lane & 7) + 8*(lane >> 4);
    const int bChk = (lane >> 3) & 1;

    load_stage4(sb + 0*STAGE_B, pAh, pAl, pBh, pBl, lda, ldb, 0,   tid);
    load_stage4(sb + 1*STAGE_B, pAh, pAl, pBh, pBl, lda, ldb, BKh, tid);

    int stidx = 0;
    for (int kb = 0; kb < kbn; kb++){
        const uint32_t aTh = sb + stidx*STAGE_B;
        const uint32_t aTl = aTh + TILE_B;
        const uint32_t bTh = aTh + 2*TILE_B;
        const uint32_t bTl = aTh + 3*TILE_B;
        CP_WAIT1();
        __syncthreads();

#pragma unroll
        for (int s = 0; s < 2; s++){
            uint32_t ah[2][4], al[2][4], bh[4][4], bl[4][4];
#pragma unroll
            for (int mt = 0; mt < 2; mt++)
                ldsm4(ah[mt], aTh + sw_off(aRow + mt*16, 2*s + aChk));
#pragma unroll
            for (int np = 0; np < 4; np++)
                ldsm4(bh[np], bTh + sw_off(bRow + np*16, 2*s + bChk));
            // p0 = Ah * Bh
#pragma unroll
            for (int mt = 0; mt < 2; mt++)
#pragma unroll
                for (int nt = 0; nt < 8; nt++){
                    const uint32_t* bb = bh[nt >> 1];
                    const int o = (nt & 1) * 2;
                    hmma(acc[mt][nt], ah[mt], bb[o], bb[o+1]);
                }
            // p1 = Al * Bh
#pragma unroll
            for (int mt = 0; mt < 2; mt++)
                ldsm4(al[mt], aTl + sw_off(aRow + mt*16, 2*s + aChk));
#pragma unroll
            for (int mt = 0; mt < 2; mt++)
#pragma unroll
                for (int nt = 0; nt < 8; nt++){
                    const uint32_t* bb = bh[nt >> 1];
                    const int o = (nt & 1) * 2;
                    hmma(acc[mt][nt], al[mt], bb[o], bb[o+1]);
                }
            // p2 = Ah * Bl
#pragma unroll
            for (int np = 0; np < 4; np++)
                ldsm4(bl[np], bTl + sw_off(bRow + np*16, 2*s + bChk));
#pragma unroll
            for (int mt = 0; mt < 2; mt++)
#pragma unroll
                for (int nt = 0; nt < 8; nt++){
                    const uint32_t* bb = bl[nt >> 1];
                    const int o = (nt & 1) * 2;
                    hmma(acc[mt][nt], ah[mt], bb[o], bb[o+1]);
                }
        }
        // NOTE: no trailing __syncthreads needed — next iteration's top barrier
        // orders these loads (into stage (kb+2)%3 == (kb-1)%3) against all warps'
        // compute of stage kb-1, which completed before they passed this kb's top barrier.
        if (kb + 2 < kbn){
            const int nidx = (stidx + 2 >= NSTAGE) ? stidx + 2 - NSTAGE : stidx + 2;
            load_stage4(sb + nidx*STAGE_B, pAh, pAl, pBh, pBl, lda, ldb, (kb+2)*BKh, tid);
        }
        stidx = (stidx + 1 == NSTAGE) ? 0 : stidx + 1;
    }

    // epilogue
    float invden = 1.0f;
    const float* knz = nullptr;
    if (MODE == E_LOGIT){
        invden = 1.0f / (fabsf(tau[0]) + 1e-6f);
        knz = knArr + (size_t)z * Sn;
    }
    const int rr = lane >> 2;
    const int cc = (lane & 3) * 2;
#pragma unroll
    for (int mt = 0; mt < 2; mt++){
#pragma unroll
        for (int nt = 0; nt < 8; nt++){
#pragma unroll
            for (int half = 0; half < 2; half++){
                int grow = mbase + wm*32 + mt*16 + rr + half*8;
                int gcol = nbase + wn*64 + nt*8 + cc;
                float v0 = acc[mt][nt][half*2 + 0];
                float v1 = acc[mt][nt][half*2 + 1];
                if (MODE == E_LOGIT){
                    v0 = (2.0f*v0 - knz[gcol])   * invden;
                    v1 = (2.0f*v1 - knz[gcol+1]) * invden;
                }
                if (MODE == E_SPLITPV){
                    bf16* dh = (nbase < HDn) ? OH : OH2;
                    bf16* dl = (nbase < HDn) ? OL : OL2;
                    size_t off = (size_t)grow*HIDn + (size_t)z*HDn + (gcol & (HDn-1));
                    bf16 h0 = __float2bfloat16(v0);
                    bf16 h1 = __float2bfloat16(v1);
                    __nv_bfloat162 hh; hh.x = h0; hh.y = h1;
                    __nv_bfloat162 ll;
                    ll.x = __float2bfloat16(v0 - __bfloat162float(h0));
                    ll.y = __float2bfloat16(v1 - __bfloat162float(h1));
                    *(__nv_bfloat162*)(dh + off) = hh;
                    *(__nv_bfloat162*)(dl + off) = ll;
                } else {
                    float2 vv = make_float2(v0, v1);
                    float* dst = C + (size_t)z*sC + (size_t)grow*ldc + gcol;
                    *(float2*)dst = vv;
                }
            }
        }
    }
}

// ---------------- elementwise: fp32 -> bf16 hi/lo ----------------
__global__ void split_kernel(const float* __restrict__ in, bf16* __restrict__ h,
                             bf16* __restrict__ l, int n)
{
    int i = blockIdx.x*blockDim.x + threadIdx.x;
    if (i < n){
        float v = in[i];
        bf16 hh = __float2bfloat16(v);
        h[i] = hh;
        l[i] = __float2bfloat16(v - __bfloat162float(hh));
    }
}

__global__ void split8_kernel(const float* __restrict__ w0, const float* __restrict__ w1,
                              const float* __restrict__ w2, const float* __restrict__ w3,
                              const float* __restrict__ w4, const float* __restrict__ w5,
                              const float* __restrict__ w6, const float* __restrict__ w7,
                              bf16* __restrict__ h, bf16* __restrict__ l)
{
    const int w = blockIdx.y;
    const float* src;
    switch (w){
        case 0: src = w0; break; case 1: src = w1; break;
        case 2: src = w2; break; case 3: src = w3; break;
        case 4: src = w4; break; case 5: src = w5; break;
        case 6: src = w6; break; default: src = w7; break;
    }
    size_t i = (size_t)blockIdx.x*blockDim.x + threadIdx.x;
    float v = src[i];
    bf16 hh = __float2bfloat16(v);
    size_t o = (size_t)w*HIDn*HIDn + i;
    h[o] = hh;
    l[o] = __float2bfloat16(v - __bfloat162float(hh));
}

// ---------------- Q/K transform: rope + exp + split + (kn) ----------------
__global__ void qk_transform(const float* __restrict__ mu, const float* __restrict__ ls,
                             const float* __restrict__ cosp, const float* __restrict__ sinp,
                             bf16* __restrict__ oh, bf16* __restrict__ ol,
                             float* __restrict__ kn)
{
    int s = blockIdx.x, h = blockIdx.y, d = threadIdx.x;
    size_t ib = (size_t)s*HIDn + h*HDn;
    float m = mu[ib + d];
    float o = mu[ib + ((d < 64) ? d + 64 : d - 64)];
    float c = cosp[s*HDn + d], sv = sinp[s*HDn + d];
    float roped = (d < 64) ? (m*c - o*sv) : (m*c + o*sv);
    float sg = expf(0.5f * ls[ib + d]);
    size_t ob = ((size_t)h*Sn + s)*DCn;
    bf16 hh = __float2bfloat16(roped);
    oh[ob + d] = hh; ol[ob + d] = __float2bfloat16(roped - __bfloat162float(hh));
    bf16 hs = __float2bfloat16(sg);
    oh[ob + 128 + d] = hs; ol[ob + 128 + d] = __float2bfloat16(sg - __bfloat162float(hs));
    if (kn){
        float acc = roped*roped + sg*sg;
#pragma unroll
        for (int off = 16; off; off >>= 1) acc += __shfl_xor_sync(0xffffffffu, acc, off);
        __shared__ float red[4];
        if ((d & 31) == 0) red[d>>5] = acc;
        __syncthreads();
        if (d == 0) kn[(size_t)h*Sn + s] = red[0] + red[1] + red[2] + red[3];
    }
}

// ---------------- V transpose + split ----------------
__global__ void v_transform(const float* __restrict__ vmu, const float* __restrict__ vls,
                            bf16* __restrict__ oh, bf16* __restrict__ ol)
{
    int i = blockIdx.x*blockDim.x + threadIdx.x;
    int s = i & (Sn-1);
    int d = (i >> 11) & (DCn-1);
    int h = i >> 19;
    float v = (d < HDn) ? vmu[(size_t)s*HIDn + h*HDn + d]
                        : vls[(size_t)s*HIDn + h*HDn + d - HDn];
    bf16 hh = __float2bfloat16(v);
    oh[i] = hh; ol[i] = __float2bfloat16(v - __bfloat162float(hh));
}

// ---------------- row softmax -> split bf16 hi/lo (vectorized) ----------------
__global__ void softmax_split(const float* __restrict__ Pg, bf16* __restrict__ Ph,
                              bf16* __restrict__ Pl)
{
    const float4* p4 = (const float4*)(Pg + (size_t)blockIdx.x * Sn);
    __nv_bfloat162* ph2 = (__nv_bfloat162*)(Ph + (size_t)blockIdx.x * Sn);
    __nv_bfloat162* pl2 = (__nv_bfloat162*)(Pl + (size_t)blockIdx.x * Sn);
    int tid = threadIdx.x;      // 256 threads, 8 elems each via 2 float4
    float4 x0 = p4[tid], x1 = p4[tid + 256];
    float v[8] = {x0.x, x0.y, x0.z, x0.w, x1.x, x1.y, x1.z, x1.w};
    float m = -1e30f;
#pragma unroll
    for (int i = 0; i < 8; i++) m = fmaxf(m, v[i]);
    __shared__ float redm[8], reds[8];
#pragma unroll
    for (int o = 16; o; o >>= 1) m = fmaxf(m, __shfl_xor_sync(0xffffffffu, m, o));
    if ((tid & 31) == 0) redm[tid>>5] = m;
    __syncthreads();
    if (tid < 32){
        float t = (tid < 8) ? redm[tid] : -1e30f;
#pragma unroll
        for (int o = 4; o; o >>= 1) t = fmaxf(t, __shfl_xor_sync(0xffffffffu, t, o));
        if (tid == 0) redm[0] = t;
    }
    __syncthreads();
    m = redm[0];
    float s = 0.f;
#pragma unroll
    for (int i = 0; i < 8; i++){ v[i] = __expf(v[i] - m); s += v[i]; }
#pragma unroll
    for (int o = 16; o; o >>= 1) s += __shfl_xor_sync(0xffffffffu, s, o);
    if ((tid & 31) == 0) reds[tid>>5] = s;
    __syncthreads();
    if (tid < 32){
        float t = (tid < 8) ? reds[tid] : 0.f;
#pragma unroll
        for (int o = 4; o; o >>= 1) t += __shfl_xor_sync(0xffffffffu, t, o);
        if (tid == 0) reds[0] = t;
    }
    __syncthreads();
    float inv = 1.f / reds[0];
#pragma unroll
    for (int c = 0; c < 2; c++){
#pragma unroll
        for (int pair = 0; pair < 2; pair++){
            float p0 = v[c*4 + pair*2 + 0] * inv;
            float p1 = v[c*4 + pair*2 + 1] * inv;
            bf16 h0 = __float2bfloat16(p0), h1 = __float2bfloat16(p1);
            __nv_bfloat162 hh; hh.x = h0; hh.y = h1;
            __nv_bfloat162 ll;
            ll.x = __float2bfloat16(p0 - __bfloat162float(h0));
            ll.y = __float2bfloat16(p1 - __bfloat162float(h1));
            int idx = (c == 0 ? 2*tid : 512 + 2*tid) + pair;
            ph2[idx] = hh;
            pl2[idx] = ll;
        }
    }
}

// ---------------- launch ----------------
extern "C" void kernel_launch(void* const* d_in, const int* in_sizes, int n_in,
                              void* d_out, int out_size)
{
    const float* xmu  = (const float*)d_in[0];
    const float* xls  = (const float*)d_in[1];
    const float* cosp = (const float*)d_in[2];
    const float* sinp = (const float*)d_in[3];
    const float* tau  = (const float*)d_in[12];
    float* out = (float*)d_out;

    bf16 *Xmu_h, *Xmu_l, *Xls_h, *Xls_l, *Wh, *Wl;
    bf16 *Qh, *Ql, *Kh, *Kl, *Vth, *Vtl, *Ph, *Pl;
    bf16 *Omh, *Oml, *Olh, *Oll;
    float *proj, *P, *kn;
    cudaGetSymbolAddress((void**)&Xmu_h, g_Xmu_h); cudaGetSymbolAddress((void**)&Xmu_l, g_Xmu_l);
    cudaGetSymbolAddress((void**)&Xls_h, g_Xls_h); cudaGetSymbolAddress((void**)&Xls_l, g_Xls_l);
    cudaGetSymbolAddress((void**)&Wh, g_W_h);      cudaGetSymbolAddress((void**)&Wl, g_W_l);
    cudaGetSymbolAddress((void**)&proj, g_proj);
    cudaGetSymbolAddress((void**)&Qh, g_Q_h);  cudaGetSymbolAddress((void**)&Ql, g_Q_l);
    cudaGetSymbolAddress((void**)&Kh, g_K_h);  cudaGetSymbolAddress((void**)&Kl, g_K_l);
    cudaGetSymbolAddress((void**)&Vth, g_Vt_h); cudaGetSymbolAddress((void**)&Vtl, g_Vt_l);
    cudaGetSymbolAddress((void**)&P, g_P);
    cudaGetSymbolAddress((void**)&Ph, g_P_h);  cudaGetSymbolAddress((void**)&Pl, g_P_l);
    cudaGetSymbolAddress((void**)&Omh, g_Om_h); cudaGetSymbolAddress((void**)&Oml, g_Om_l);
    cudaGetSymbolAddress((void**)&Olh, g_Ol_h); cudaGetSymbolAddress((void**)&Oll, g_Ol_l);
    cudaGetSymbolAddress((void**)&kn, g_kn);

    cudaFuncSetAttribute(hm_gemm<E_PLAIN>,  cudaFuncAttributeMaxDynamicSharedMemorySize, SMEM_DYN);
    cudaFuncSetAttribute(hm_gemm<E_LOGIT>,  cudaFuncAttributeMaxDynamicSharedMemorySize, SMEM_DYN);
    cudaFuncSetAttribute(hm_gemm<E_SPLITPV>,cudaFuncAttributeMaxDynamicSharedMemorySize, SMEM_DYN);

    const int NE = HIDn*HIDn;
    dim3 eb(256);

    split_kernel<<<(Sn*HIDn)/256, eb>>>(xmu, Xmu_h, Xmu_l, Sn*HIDn);
    split_kernel<<<(Sn*HIDn)/256, eb>>>(xls, Xls_h, Xls_l, Sn*HIDn);
    split8_kernel<<<dim3(NE/256, 8), eb>>>(
        (const float*)d_in[4], (const float*)d_in[5], (const float*)d_in[6], (const float*)d_in[7],
        (const float*)d_in[8], (const float*)d_in[9], (const float*)d_in[10], (const float*)d_in[11],
        Wh, Wl);

    dim3 blk(NTHR);
    size_t shm = SMEM_DYN;
    float* pq  = proj + 0*(size_t)Sn*HIDn;
    float* pqs = proj + 1*(size_t)Sn*HIDn;
    float* pk  = proj + 2*(size_t)Sn*HIDn;
    float* pks = proj + 3*(size_t)Sn*HIDn;
    float* pv  = proj + 4*(size_t)Sn*HIDn;
    float* pvs = proj + 5*(size_t)Sn*HIDn;

    dim3 gp(HIDn/BNh, Sn/BMh, 1);
    hm_gemm<E_PLAIN><<<gp, blk, shm>>>(Xmu_h, Xmu_l, Wh + 0*(size_t)NE, Wl + 0*(size_t)NE, pq,  nullptr,nullptr,nullptr,nullptr, HIDn, HIDn, HIDn, HIDn, 0,0,0, nullptr, nullptr);
    hm_gemm<E_PLAIN><<<gp, blk, shm>>>(Xmu_h, Xmu_l, Wh + 1*(size_t)NE, Wl + 1*(size_t)NE, pk,  nullptr,nullptr,nullptr,nullptr, HIDn, HIDn, HIDn, HIDn, 0,0,0, nullptr, nullptr);
    hm_gemm<E_PLAIN><<<gp, blk, shm>>>(Xmu_h, Xmu_l, Wh + 2*(size_t)NE, Wl + 2*(size_t)NE, pv,  nullptr,nullptr,nullptr,nullptr, HIDn, HIDn, HIDn, HIDn, 0,0,0, nullptr, nullptr);
    hm_gemm<E_PLAIN><<<gp, blk, shm>>>(Xls_h, Xls_l, Wh + 4*(size_t)NE, Wl + 4*(size_t)NE, pqs, nullptr,nullptr,nullptr,nullptr, HIDn, HIDn, HIDn, HIDn, 0,0,0, nullptr, nullptr);
    hm_gemm<E_PLAIN><<<gp, blk, shm>>>(Xls_h, Xls_l, Wh + 5*(size_t)NE, Wl + 5*(size_t)NE, pks, nullptr,nullptr,nullptr,nullptr, HIDn, HIDn, HIDn, HIDn, 0,0,0, nullptr, nullptr);
    hm_gemm<E_PLAIN><<<gp, blk, shm>>>(Xls_h, Xls_l, Wh + 6*(size_t)NE, Wl + 6*(size_t)NE, pvs, nullptr,nullptr,nullptr,nullptr, HIDn, HIDn, HIDn, HIDn, 0,0,0, nullptr, nullptr);

    qk_transform<<<dim3(Sn, NHn), 128>>>(pq, pqs, cosp, sinp, Qh, Ql, nullptr);
    qk_transform<<<dim3(Sn, NHn), 128>>>(pk, pks, cosp, sinp, Kh, Kl, kn);
    v_transform<<<((size_t)NHn*DCn*Sn)/256, eb>>>(pv, pvs, Vth, Vtl);

    dim3 gl(Sn/BNh, Sn/BMh, NHn);
    hm_gemm<E_LOGIT><<<gl, blk, shm>>>(Qh, Ql, Kh, Kl, P, nullptr,nullptr,nullptr,nullptr,
        DCn, DCn, DCn, Sn,
        (long long)Sn*DCn, (long long)Sn*DCn, (long long)Sn*Sn, kn, tau);

    softmax_split<<<NHn*Sn, 256>>>(P, Ph, Pl);

    dim3 gv(DCn/BNh, Sn/BMh, NHn);
    hm_gemm<E_SPLITPV><<<gv, blk, shm>>>(Ph, Pl, Vth, Vtl, nullptr, Omh, Oml, Olh, Oll,
        Sn, Sn, Sn, HIDn,
        (long long)Sn*Sn, (long long)DCn*Sn, 0, nullptr, nullptr);

    dim3 gp2(HIDn/BNh, Sn/BMh, 1);
    hm_gemm<E_PLAIN><<<gp2, blk, shm>>>(Omh, Oml, Wh + 3*(size_t)NE, Wl + 3*(size_t)NE, out,                    nullptr,nullptr,nullptr,nullptr, HIDn, HIDn, HIDn, HIDn, 0,0,0, nullptr, nullptr);
    hm_gemm<E_PLAIN><<<gp2, blk, shm>>>(Olh, Oll, Wh + 7*(size_t)NE, Wl + 7*(size_t)NE, out + (size_t)Sn*HIDn, nullptr,nullptr,nullptr,nullptr, HIDn, HIDn, HIDn, HIDn, 0,0,0, nullptr, nullptr);
}

// round 8
// speedup vs baseline: 3.1246x; 1.0682x over previous
#include <cuda_runtime.h>
#include <cuda_bf16.h>
#include <math.h>
#include <stdint.h>

typedef __nv_bfloat16 bf16;

#define Sn   2048
#define HIDn 2048
#define NHn  16
#define HDn  128
#define DCn  256

#define BMh  128
#define BNh  128
#define BKh  32
#define NTHR 256
#define ROWB 64
#define TILE_B (BMh * ROWB)            // 8KB per operand tile
#define STAGE_B (4 * TILE_B)           // Ah, Al, Bh, Bl = 32KB per stage
#define NSTAGE 3
#define SMEM_DYN (NSTAGE * STAGE_B)    // 96KB

// ---------------- device globals (scratch) ----------------
static __device__ __align__(1024) bf16 g_Xmu_h[Sn*HIDn], g_Xmu_l[Sn*HIDn];
static __device__ __align__(1024) bf16 g_Xls_h[Sn*HIDn], g_Xls_l[Sn*HIDn];
static __device__ __align__(1024) bf16 g_W_h[8][HIDn*HIDn];
static __device__ __align__(1024) bf16 g_W_l[8][HIDn*HIDn];
static __device__ __align__(1024) float g_proj[6][(size_t)Sn*HIDn];
static __device__ __align__(1024) bf16 g_Q_h[(size_t)NHn*Sn*DCn], g_Q_l[(size_t)NHn*Sn*DCn];
static __device__ __align__(1024) bf16 g_K_h[(size_t)NHn*Sn*DCn], g_K_l[(size_t)NHn*Sn*DCn];
static __device__ __align__(1024) bf16 g_Vt_h[(size_t)NHn*DCn*Sn], g_Vt_l[(size_t)NHn*DCn*Sn];
static __device__ __align__(1024) float g_P[(size_t)NHn*Sn*Sn];
static __device__ __align__(1024) bf16 g_P_h[(size_t)NHn*Sn*Sn], g_P_l[(size_t)NHn*Sn*Sn];
static __device__ __align__(1024) bf16 g_Om_h[Sn*HIDn], g_Om_l[Sn*HIDn];
static __device__ __align__(1024) bf16 g_Ol_h[Sn*HIDn], g_Ol_l[Sn*HIDn];
static __device__ float g_kn[NHn*Sn];

// ---------------- helpers ----------------
__device__ __forceinline__ uint32_t smem_u32(const void* p){
    uint32_t a;
    asm("{ .reg .u64 t; cvta.to.shared.u64 t, %1; cvt.u32.u64 %0, t; }" : "=r"(a) : "l"(p));
    return a;
}
__device__ __forceinline__ void cp16(uint32_t dst, const void* src){
    asm volatile("cp.async.cg.shared.global [%0], [%1], 16;" :: "r"(dst), "l"(src) : "memory");
}
#define CP_COMMIT() asm volatile("cp.async.commit_group;" ::: "memory")
#define CP_WAIT1()  asm volatile("cp.async.wait_group 1;" ::: "memory")

__device__ __forceinline__ void ldsm4(uint32_t* r, uint32_t addr){
    asm volatile("ldmatrix.sync.aligned.m8n8.x4.shared.b16 {%0,%1,%2,%3}, [%4];"
                 : "=r"(r[0]), "=r"(r[1]), "=r"(r[2]), "=r"(r[3]) : "r"(addr));
}
__device__ __forceinline__ void hmma(float* d, const uint32_t* a, uint32_t b0, uint32_t b1){
    asm volatile("mma.sync.aligned.m16n8k16.row.col.f32.bf16.bf16.f32 "
                 "{%0,%1,%2,%3}, {%4,%5,%6,%7}, {%8,%9}, {%0,%1,%2,%3};"
                 : "+f"(d[0]), "+f"(d[1]), "+f"(d[2]), "+f"(d[3])
                 : "r"(a[0]), "r"(a[1]), "r"(a[2]), "r"(a[3]), "r"(b0), "r"(b1));
}
__device__ __forceinline__ uint32_t sw_off(int row, int chunk){
    return (uint32_t)(row * ROWB + ((chunk ^ ((row >> 1) & 3)) << 4));
}

// ---------------- 4-tile stage loader ----------------
__device__ __forceinline__ void load_stage4(uint32_t st,
    const bf16* __restrict__ Ah, const bf16* __restrict__ Al,
    const bf16* __restrict__ Bh, const bf16* __restrict__ Bl,
    int lda, int ldb, int koff, int tid)
{
#pragma unroll
    for (int i = 0; i < 8; i++){
        const int tile = i >> 1;
        const int id = tid + i*NTHR;
        const int r = (id >> 2) & 127;
        const int c = id & 3;
        const bf16* base = (tile==0) ? Ah : (tile==1) ? Al : (tile==2) ? Bh : Bl;
        const int ld = (tile < 2) ? lda : ldb;
        cp16(st + tile*TILE_B + sw_off(r, c), base + (size_t)r*ld + koff + c*8);
    }
    CP_COMMIT();
}

enum { E_LOGIT = 1, E_SPLITPV = 2, E_PROJ6 = 3, E_OUT2 = 4 };

// ---------------- HMMA GEMM: C[M,N] = (Ah+Al)(Bh+Bl)^T via bf16x3 ----------------
// E_PROJ6: z in 0..5 picks A source (z<3: A / else A2) and weight wsel=(z<3?z:z+1),
//          C = Cbase + z*S*HID.
// E_OUT2:  z in 0..1 picks A (z? A2 : A) and weight (z? 7 : 3), C = Cbase + z*S*HID.
// E_LOGIT/E_SPLITPV: batched over z with explicit strides; B operands in WhB/WlB.
template<int MODE>
__global__ void __launch_bounds__(NTHR, 2)
hm_gemm(const bf16* __restrict__ Ah, const bf16* __restrict__ Al,
        const bf16* __restrict__ A2h, const bf16* __restrict__ A2l,
        const bf16* __restrict__ WhB, const bf16* __restrict__ WlB,
        float* __restrict__ C,
        bf16* __restrict__ OH, bf16* __restrict__ OL,
        bf16* __restrict__ OH2, bf16* __restrict__ OL2,
        int K, int lda, int ldb, int ldc,
        long long sA, long long sB, long long sC,
        const float* __restrict__ knArr, const float* __restrict__ tau)
{
    extern __shared__ __align__(128) char smem[];
    const uint32_t sb = smem_u32(smem);
    const int tid  = threadIdx.x;
    const int lane = tid & 31;
    const int wid  = tid >> 5;
    const int wm = wid & 3;
    const int wn = wid >> 2;
    const int z = blockIdx.z;
    const int mbase = blockIdx.y * BMh, nbase = blockIdx.x * BNh;

    const bf16 *bAh, *bAl, *bBh, *bBl;
    float* Cz = C;
    if (MODE == E_PROJ6){
        const bool ls = (z >= 3);
        bAh = ls ? A2h : Ah;  bAl = ls ? A2l : Al;
        const int wsel = ls ? (z + 1) : z;
        bBh = WhB + (size_t)wsel*HIDn*HIDn;
        bBl = WlB + (size_t)wsel*HIDn*HIDn;
        Cz = C + (size_t)z*Sn*HIDn;
    } else if (MODE == E_OUT2){
        bAh = z ? A2h : Ah;  bAl = z ? A2l : Al;
        const int wsel = z ? 7 : 3;
        bBh = WhB + (size_t)wsel*HIDn*HIDn;
        bBl = WlB + (size_t)wsel*HIDn*HIDn;
        Cz = C + (size_t)z*Sn*HIDn;
    } else {
        bAh = Ah + (size_t)z*sA;  bAl = Al + (size_t)z*sA;
        bBh = WhB + (size_t)z*sB; bBl = WlB + (size_t)z*sB;
        Cz = C + (size_t)z*sC;
    }
    const bf16* pAh = bAh + (size_t)mbase*lda;
    const bf16* pAl = bAl + (size_t)mbase*lda;
    const bf16* pBh = bBh + (size_t)nbase*ldb;
    const bf16* pBl = bBl + (size_t)nbase*ldb;

    const int kbn = K / BKh;

    float acc[2][8][4];
#pragma unroll
    for (int i = 0; i < 2; i++)
#pragma unroll
        for (int j = 0; j < 8; j++)
#pragma unroll
            for (int q = 0; q < 4; q++) acc[i][j][q] = 0.f;

    const int aRow = wm*32 + (lane & 7) + 8*((lane >> 3) & 1);
    const int aChk = lane >> 4;
    const int bRow = wn*64 + (lane & 7) + 8*(lane >> 4);
    const int bChk = (lane >> 3) & 1;

    load_stage4(sb + 0*STAGE_B, pAh, pAl, pBh, pBl, lda, ldb, 0,   tid);
    load_stage4(sb + 1*STAGE_B, pAh, pAl, pBh, pBl, lda, ldb, BKh, tid);

    int stidx = 0;
    for (int kb = 0; kb < kbn; kb++){
        const uint32_t aTh = sb + stidx*STAGE_B;
        const uint32_t aTl = aTh + TILE_B;
        const uint32_t bTh = aTh + 2*TILE_B;
        const uint32_t bTl = aTh + 3*TILE_B;
        CP_WAIT1();
        __syncthreads();

#pragma unroll
        for (int s = 0; s < 2; s++){
            uint32_t ah[2][4], al[2][4], bh[4][4], bl[4][4];
#pragma unroll
            for (int mt = 0; mt < 2; mt++)
                ldsm4(ah[mt], aTh + sw_off(aRow + mt*16, 2*s + aChk));
#pragma unroll
            for (int np = 0; np < 4; np++)
                ldsm4(bh[np], bTh + sw_off(bRow + np*16, 2*s + bChk));
#pragma unroll
            for (int mt = 0; mt < 2; mt++)
#pragma unroll
                for (int nt = 0; nt < 8; nt++){
                    const uint32_t* bb = bh[nt >> 1];
                    const int o = (nt & 1) * 2;
                    hmma(acc[mt][nt], ah[mt], bb[o], bb[o+1]);
                }
#pragma unroll
            for (int mt = 0; mt < 2; mt++)
                ldsm4(al[mt], aTl + sw_off(aRow + mt*16, 2*s + aChk));
#pragma unroll
            for (int mt = 0; mt < 2; mt++)
#pragma unroll
                for (int nt = 0; nt < 8; nt++){
                    const uint32_t* bb = bh[nt >> 1];
                    const int o = (nt & 1) * 2;
                    hmma(acc[mt][nt], al[mt], bb[o], bb[o+1]);
                }
#pragma unroll
            for (int np = 0; np < 4; np++)
                ldsm4(bl[np], bTl + sw_off(bRow + np*16, 2*s + bChk));
#pragma unroll
            for (int mt = 0; mt < 2; mt++)
#pragma unroll
                for (int nt = 0; nt < 8; nt++){
                    const uint32_t* bb = bl[nt >> 1];
                    const int o = (nt & 1) * 2;
                    hmma(acc[mt][nt], ah[mt], bb[o], bb[o+1]);
                }
        }
        // no trailing barrier: next iteration's top barrier orders these loads
        if (kb + 2 < kbn){
            const int nidx = (stidx + 2 >= NSTAGE) ? stidx + 2 - NSTAGE : stidx + 2;
            load_stage4(sb + nidx*STAGE_B, pAh, pAl, pBh, pBl, lda, ldb, (kb+2)*BKh, tid);
        }
        stidx = (stidx + 1 == NSTAGE) ? 0 : stidx + 1;
    }

    // epilogue
    float invden = 1.0f;
    const float* knz = nullptr;
    if (MODE == E_LOGIT){
        invden = 1.0f / (fabsf(tau[0]) + 1e-6f);
        knz = knArr + (size_t)z * Sn;
    }
    const int rr = lane >> 2;
    const int cc = (lane & 3) * 2;
#pragma unroll
    for (int mt = 0; mt < 2; mt++){
#pragma unroll
        for (int nt = 0; nt < 8; nt++){
#pragma unroll
            for (int half = 0; half < 2; half++){
                int grow = mbase + wm*32 + mt*16 + rr + half*8;
                int gcol = nbase + wn*64 + nt*8 + cc;
                float v0 = acc[mt][nt][half*2 + 0];
                float v1 = acc[mt][nt][half*2 + 1];
                if (MODE == E_LOGIT){
                    v0 = (2.0f*v0 - knz[gcol])   * invden;
                    v1 = (2.0f*v1 - knz[gcol+1]) * invden;
                }
                if (MODE == E_SPLITPV){
                    bf16* dh = (nbase < HDn) ? OH : OH2;
                    bf16* dl = (nbase < HDn) ? OL : OL2;
                    size_t off = (size_t)grow*HIDn + (size_t)z*HDn + (gcol & (HDn-1));
                    bf16 h0 = __float2bfloat16(v0);
                    bf16 h1 = __float2bfloat16(v1);
                    __nv_bfloat162 hh; hh.x = h0; hh.y = h1;
                    __nv_bfloat162 ll;
                    ll.x = __float2bfloat16(v0 - __bfloat162float(h0));
                    ll.y = __float2bfloat16(v1 - __bfloat162float(h1));
                    *(__nv_bfloat162*)(dh + off) = hh;
                    *(__nv_bfloat162*)(dl + off) = ll;
                } else {
                    float2 vv = make_float2(v0, v1);
                    float* dst = Cz + (size_t)grow*ldc + gcol;
                    *(float2*)dst = vv;
                }
            }
        }
    }
}

// ---------------- elementwise: fp32 -> bf16 hi/lo ----------------
__global__ void split_kernel(const float* __restrict__ in, bf16* __restrict__ h,
                             bf16* __restrict__ l, int n)
{
    int i = blockIdx.x*blockDim.x + threadIdx.x;
    if (i < n){
        float v = in[i];
        bf16 hh = __float2bfloat16(v);
        h[i] = hh;
        l[i] = __float2bfloat16(v - __bfloat162float(hh));
    }
}

__global__ void split8_kernel(const float* __restrict__ w0, const float* __restrict__ w1,
                              const float* __restrict__ w2, const float* __restrict__ w3,
                              const float* __restrict__ w4, const float* __restrict__ w5,
                              const float* __restrict__ w6, const float* __restrict__ w7,
                              bf16* __restrict__ h, bf16* __restrict__ l)
{
    const int w = blockIdx.y;
    const float* src;
    switch (w){
        case 0: src = w0; break; case 1: src = w1; break;
        case 2: src = w2; break; case 3: src = w3; break;
        case 4: src = w4; break; case 5: src = w5; break;
        case 6: src = w6; break; default: src = w7; break;
    }
    size_t i = (size_t)blockIdx.x*blockDim.x + threadIdx.x;
    float v = src[i];
    bf16 hh = __float2bfloat16(v);
    size_t o = (size_t)w*HIDn*HIDn + i;
    h[o] = hh;
    l[o] = __float2bfloat16(v - __bfloat162float(hh));
}

// ---------------- Q/K transform: rope + exp + split + (kn) ----------------
__global__ void qk_transform(const float* __restrict__ mu, const float* __restrict__ ls,
                             const float* __restrict__ cosp, const float* __restrict__ sinp,
                             bf16* __restrict__ oh, bf16* __restrict__ ol,
                             float* __restrict__ kn)
{
    int s = blockIdx.x, h = blockIdx.y, d = threadIdx.x;
    size_t ib = (size_t)s*HIDn + h*HDn;
    float m = mu[ib + d];
    float o = mu[ib + ((d < 64) ? d + 64 : d - 64)];
    float c = cosp[s*HDn + d], sv = sinp[s*HDn + d];
    float roped = (d < 64) ? (m*c - o*sv) : (m*c + o*sv);
    float sg = expf(0.5f * ls[ib + d]);
    size_t ob = ((size_t)h*Sn + s)*DCn;
    bf16 hh = __float2bfloat16(roped);
    oh[ob + d] = hh; ol[ob + d] = __float2bfloat16(roped - __bfloat162float(hh));
    bf16 hs = __float2bfloat16(sg);
    oh[ob + 128 + d] = hs; ol[ob + 128 + d] = __float2bfloat16(sg - __bfloat162float(hs));
    if (kn){
        float acc = roped*roped + sg*sg;
#pragma unroll
        for (int off = 16; off; off >>= 1) acc += __shfl_xor_sync(0xffffffffu, acc, off);
        __shared__ float red[4];
        if ((d & 31) == 0) red[d>>5] = acc;
        __syncthreads();
        if (d == 0) kn[(size_t)h*Sn + s] = red[0] + red[1] + red[2] + red[3];
    }
}

// ---------------- V transpose + split ----------------
__global__ void v_transform(const float* __restrict__ vmu, const float* __restrict__ vls,
                            bf16* __restrict__ oh, bf16* __restrict__ ol)
{
    int i = blockIdx.x*blockDim.x + threadIdx.x;
    int s = i & (Sn-1);
    int d = (i >> 11) & (DCn-1);
    int h = i >> 19;
    float v = (d < HDn) ? vmu[(size_t)s*HIDn + h*HDn + d]
                        : vls[(size_t)s*HIDn + h*HDn + d - HDn];
    bf16 hh = __float2bfloat16(v);
    oh[i] = hh; ol[i] = __float2bfloat16(v - __bfloat162float(hh));
}

// ---------------- row softmax -> split bf16 hi/lo (vectorized) ----------------
__global__ void softmax_split(const float* __restrict__ Pg, bf16* __restrict__ Ph,
                              bf16* __restrict__ Pl)
{
    const float4* p4 = (const float4*)(Pg + (size_t)blockIdx.x * Sn);
    __nv_bfloat162* ph2 = (__nv_bfloat162*)(Ph + (size_t)blockIdx.x * Sn);
    __nv_bfloat162* pl2 = (__nv_bfloat162*)(Pl + (size_t)blockIdx.x * Sn);
    int tid = threadIdx.x;
    float4 x0 = p4[tid], x1 = p4[tid + 256];
    float v[8] = {x0.x, x0.y, x0.z, x0.w, x1.x, x1.y, x1.z, x1.w};
    float m = -1e30f;
#pragma unroll
    for (int i = 0; i < 8; i++) m = fmaxf(m, v[i]);
    __shared__ float redm[8], reds[8];
#pragma unroll
    for (int o = 16; o; o >>= 1) m = fmaxf(m, __shfl_xor_sync(0xffffffffu, m, o));
    if ((tid & 31) == 0) redm[tid>>5] = m;
    __syncthreads();
    if (tid < 32){
        float t = (tid < 8) ? redm[tid] : -1e30f;
#pragma unroll
        for (int o = 4; o; o >>= 1) t = fmaxf(t, __shfl_xor_sync(0xffffffffu, t, o));
        if (tid == 0) redm[0] = t;
    }
    __syncthreads();
    m = redm[0];
    float s = 0.f;
#pragma unroll
    for (int i = 0; i < 8; i++){ v[i] = __expf(v[i] - m); s += v[i]; }
#pragma unroll
    for (int o = 16; o; o >>= 1) s += __shfl_xor_sync(0xffffffffu, s, o);
    if ((tid & 31) == 0) reds[tid>>5] = s;
    __syncthreads();
    if (tid < 32){
        float t = (tid < 8) ? reds[tid] : 0.f;
#pragma unroll
        for (int o = 4; o; o >>= 1) t += __shfl_xor_sync(0xffffffffu, t, o);
        if (tid == 0) reds[0] = t;
    }
    __syncthreads();
    float inv = 1.f / reds[0];
#pragma unroll
    for (int c = 0; c < 2; c++){
#pragma unroll
        for (int pair = 0; pair < 2; pair++){
            float p0 = v[c*4 + pair*2 + 0] * inv;
            float p1 = v[c*4 + pair*2 + 1] * inv;
            bf16 h0 = __float2bfloat16(p0), h1 = __float2bfloat16(p1);
            __nv_bfloat162 hh; hh.x = h0; hh.y = h1;
            __nv_bfloat162 ll;
            ll.x = __float2bfloat16(p0 - __bfloat162float(h0));
            ll.y = __float2bfloat16(p1 - __bfloat162float(h1));
            int idx = (c == 0 ? 2*tid : 512 + 2*tid) + pair;
            ph2[idx] = hh;
            pl2[idx] = ll;
        }
    }
}

// ---------------- launch ----------------
extern "C" void kernel_launch(void* const* d_in, const int* in_sizes, int n_in,
                              void* d_out, int out_size)
{
    const float* xmu  = (const float*)d_in[0];
    const float* xls  = (const float*)d_in[1];
    const float* cosp = (const float*)d_in[2];
    const float* sinp = (const float*)d_in[3];
    const float* tau  = (const float*)d_in[12];
    float* out = (float*)d_out;

    bf16 *Xmu_h, *Xmu_l, *Xls_h, *Xls_l, *Wh, *Wl;
    bf16 *Qh, *Ql, *Kh, *Kl, *Vth, *Vtl, *Ph, *Pl;
    bf16 *Omh, *Oml, *Olh, *Oll;
    float *proj, *P, *kn;
    cudaGetSymbolAddress((void**)&Xmu_h, g_Xmu_h); cudaGetSymbolAddress((void**)&Xmu_l, g_Xmu_l);
    cudaGetSymbolAddress((void**)&Xls_h, g_Xls_h); cudaGetSymbolAddress((void**)&Xls_l, g_Xls_l);
    cudaGetSymbolAddress((void**)&Wh, g_W_h);      cudaGetSymbolAddress((void**)&Wl, g_W_l);
    cudaGetSymbolAddress((void**)&proj, g_proj);
    cudaGetSymbolAddress((void**)&Qh, g_Q_h);  cudaGetSymbolAddress((void**)&Ql, g_Q_l);
    cudaGetSymbolAddress((void**)&Kh, g_K_h);  cudaGetSymbolAddress((void**)&Kl, g_K_l);
    cudaGetSymbolAddress((void**)&Vth, g_Vt_h); cudaGetSymbolAddress((void**)&Vtl, g_Vt_l);
    cudaGetSymbolAddress((void**)&P, g_P);
    cudaGetSymbolAddress((void**)&Ph, g_P_h);  cudaGetSymbolAddress((void**)&Pl, g_P_l);
    cudaGetSymbolAddress((void**)&Omh, g_Om_h); cudaGetSymbolAddress((void**)&Oml, g_Om_l);
    cudaGetSymbolAddress((void**)&Olh, g_Ol_h); cudaGetSymbolAddress((void**)&Oll, g_Ol_l);
    cudaGetSymbolAddress((void**)&kn, g_kn);

    cudaFuncSetAttribute(hm_gemm<E_PROJ6>, cudaFuncAttributeMaxDynamicSharedMemorySize, SMEM_DYN);
    cudaFuncSetAttribute(hm_gemm<E_OUT2>,  cudaFuncAttributeMaxDynamicSharedMemorySize, SMEM_DYN);
    cudaFuncSetAttribute(hm_gemm<E_LOGIT>, cudaFuncAttributeMaxDynamicSharedMemorySize, SMEM_DYN);
    cudaFuncSetAttribute(hm_gemm<E_SPLITPV>,cudaFuncAttributeMaxDynamicSharedMemorySize, SMEM_DYN);

    const int NE = HIDn*HIDn;
    dim3 eb(256);

    split_kernel<<<(Sn*HIDn)/256, eb>>>(xmu, Xmu_h, Xmu_l, Sn*HIDn);
    split_kernel<<<(Sn*HIDn)/256, eb>>>(xls, Xls_h, Xls_l, Sn*HIDn);
    split8_kernel<<<dim3(NE/256, 8), eb>>>(
        (const float*)d_in[4], (const float*)d_in[5], (const float*)d_in[6], (const float*)d_in[7],
        (const float*)d_in[8], (const float*)d_in[9], (const float*)d_in[10], (const float*)d_in[11],
        Wh, Wl);

    dim3 blk(NTHR);
    size_t shm = SMEM_DYN;
    float* pq  = proj + 0*(size_t)Sn*HIDn;
    float* pqs = proj + 1*(size_t)Sn*HIDn;
    float* pk  = proj + 2*(size_t)Sn*HIDn;
    float* pks = proj + 3*(size_t)Sn*HIDn;
    float* pv  = proj + 4*(size_t)Sn*HIDn;
    float* pvs = proj + 5*(size_t)Sn*HIDn;

    // all six projections in ONE launch: z -> {q,k,v}(mu), {qs,ks,vs}(ls)
    // wsel mapping inside kernel: z<3 -> W[z] (Wq,Wk,Wv), z>=3 -> W[z+1] (Wqs,Wks,Wvs)
    // dst: proj + z*S*HID in order [q, k, v, qs, ks, vs]
    dim3 gp6(HIDn/BNh, Sn/BMh, 6);
    hm_gemm<E_PROJ6><<<gp6, blk, shm>>>(Xmu_h, Xmu_l, Xls_h, Xls_l, Wh, Wl,
        proj, nullptr,nullptr,nullptr,nullptr,
        HIDn, HIDn, HIDn, HIDn, 0,0,0, nullptr, nullptr);

    // NOTE: proj layout is now [q, k, v, qs, ks, vs] (z order above)
    qk_transform<<<dim3(Sn, NHn), 128>>>(proj + 0*(size_t)Sn*HIDn, proj + 3*(size_t)Sn*HIDn, cosp, sinp, Qh, Ql, nullptr);
    qk_transform<<<dim3(Sn, NHn), 128>>>(proj + 1*(size_t)Sn*HIDn, proj + 4*(size_t)Sn*HIDn, cosp, sinp, Kh, Kl, kn);
    v_transform<<<((size_t)NHn*DCn*Sn)/256, eb>>>(proj + 2*(size_t)Sn*HIDn, proj + 5*(size_t)Sn*HIDn, Vth, Vtl);

    dim3 gl(Sn/BNh, Sn/BMh, NHn);
    hm_gemm<E_LOGIT><<<gl, blk, shm>>>(Qh, Ql, nullptr, nullptr, Kh, Kl, P,
        nullptr,nullptr,nullptr,nullptr,
        DCn, DCn, DCn, Sn,
        (long long)Sn*DCn, (long long)Sn*DCn, (long long)Sn*Sn, kn, tau);

    softmax_split<<<NHn*Sn, 256>>>(P, Ph, Pl);

    dim3 gv(DCn/BNh, Sn/BMh, NHn);
    hm_gemm<E_SPLITPV><<<gv, blk, shm>>>(Ph, Pl, nullptr, nullptr, Vth, Vtl, nullptr,
        Omh, Oml, Olh, Oll,
        Sn, Sn, Sn, HIDn,
        (long long)Sn*Sn, (long long)DCn*Sn, 0, nullptr, nullptr);

    // both output projections in ONE launch: z=0 -> Om x W3, z=1 -> Ol x W7
    dim3 go2(HIDn/BNh, Sn/BMh, 2);
    hm_gemm<E_OUT2><<<go2, blk, shm>>>(Omh, Oml, Olh, Oll, Wh, Wl,
        out, nullptr,nullptr,nullptr,nullptr,
        HIDn, HIDn, HIDn, HIDn, 0,0,0, nullptr, nullptr);
}